// round 1
// baseline (speedup 1.0000x reference)
#include <cuda_runtime.h>
#include <cstdint>
#include <cstddef>

#define Bb 2
#define Ss 2048
#define Hh 1024
#define NHh 16
#define HDd 64
#define NTt 5
#define TOKS (Bb*Ss)          /* 4096 */
#define SCALE 0.125f          /* 1/sqrt(64) */

// ---------------- scratch (static device globals; no allocation) ----------------
__device__ float g_q[(size_t)TOKS*Hh];
__device__ float g_k[(size_t)TOKS*Hh];
__device__ float g_v[(size_t)TOKS*Hh];
__device__ float g_qt[(size_t)TOKS*HDd];
__device__ float g_kt[(size_t)TOKS*HDd];
__device__ float g_qtW[(size_t)Bb*NHh*Ss*HDd];
__device__ float g_attn[(size_t)TOKS*Hh];

// ---------------- generic C = A @ W^T + bias ----------------
// A:[M,K] row-major, W:[N,K] row-major, C:[M,N]. M,N mult of 64, K mult of 16.
__global__ __launch_bounds__(256)
void gemm_nt_bias(const float* __restrict__ A, const float* __restrict__ W,
                  const float* __restrict__ bias, float* __restrict__ C,
                  int M, int N, int K)
{
    __shared__ float As[16][64];
    __shared__ float Ws[16][64];
    int bm = blockIdx.y * 64, bn = blockIdx.x * 64;
    int tid = threadIdx.x;
    int tx = tid & 15, ty = tid >> 4;
    int lr = tid >> 2;          // 0..63
    int lc = (tid & 3) * 4;     // 0,4,8,12
    float acc[4][4];
#pragma unroll
    for (int i = 0; i < 4; i++)
#pragma unroll
        for (int j = 0; j < 4; j++) acc[i][j] = 0.f;

    for (int k0 = 0; k0 < K; k0 += 16) {
        float4 a4 = *(const float4*)(A + (size_t)(bm + lr) * K + k0 + lc);
        float4 w4 = *(const float4*)(W + (size_t)(bn + lr) * K + k0 + lc);
        As[lc + 0][lr] = a4.x; As[lc + 1][lr] = a4.y; As[lc + 2][lr] = a4.z; As[lc + 3][lr] = a4.w;
        Ws[lc + 0][lr] = w4.x; Ws[lc + 1][lr] = w4.y; Ws[lc + 2][lr] = w4.z; Ws[lc + 3][lr] = w4.w;
        __syncthreads();
#pragma unroll
        for (int kk = 0; kk < 16; kk++) {
            float a[4], b[4];
#pragma unroll
            for (int i = 0; i < 4; i++) a[i] = As[kk][ty * 4 + i];
#pragma unroll
            for (int j = 0; j < 4; j++) b[j] = Ws[kk][tx * 4 + j];
#pragma unroll
            for (int i = 0; i < 4; i++)
#pragma unroll
                for (int j = 0; j < 4; j++) acc[i][j] += a[i] * b[j];
        }
        __syncthreads();
    }
#pragma unroll
    for (int i = 0; i < 4; i++) {
        int row = bm + ty * 4 + i, col = bn + tx * 4;
        float4 o;
        o.x = acc[i][0] + bias[col + 0];
        o.y = acc[i][1] + bias[col + 1];
        o.z = acc[i][2] + bias[col + 2];
        o.w = acc[i][3] + bias[col + 3];
        *(float4*)(C + (size_t)row * N + col) = o;
    }
}

// ---------------- type inference: logits, softmax(5), latent, qt, kt ----------------
__global__ __launch_bounds__(128)
void type_kernel(const float* __restrict__ x, const float* __restrict__ Wti,
                 const float* __restrict__ bti, const float* __restrict__ temb,
                 const float* __restrict__ Wqt, const float* __restrict__ bqt,
                 const float* __restrict__ Wkt, const float* __restrict__ bkt,
                 float* __restrict__ tl_out, float* __restrict__ qt, float* __restrict__ kt)
{
    int tok = blockIdx.x;
    int tid = threadIdx.x;
    __shared__ float xs[Hh];
    __shared__ float red[128];
    __shared__ float probs[NTt];
    __shared__ float latent[HDd];

    const float* xr = x + (size_t)tok * Hh;
    for (int i = tid; i < Hh; i += 128) xs[i] = xr[i];
    __syncthreads();

    float lg[NTt];
    for (int t = 0; t < NTt; t++) {
        float p = 0.f;
        for (int hh = tid; hh < Hh; hh += 128) p += xs[hh] * Wti[(size_t)t * Hh + hh];
        __syncthreads();
        red[tid] = p;
        __syncthreads();
        for (int s = 64; s > 0; s >>= 1) {
            if (tid < s) red[tid] += red[tid + s];
            __syncthreads();
        }
        lg[t] = red[0] + bti[t];
    }
    if (tid == 0) {
        float mx = lg[0];
        for (int t = 1; t < NTt; t++) mx = fmaxf(mx, lg[t]);
        float se = 0.f;
        for (int t = 0; t < NTt; t++) { float e = expf(lg[t] - mx); probs[t] = e; se += e; }
        float inv = 1.f / se;
        for (int t = 0; t < NTt; t++) probs[t] *= inv;
    }
    if (tid < NTt) tl_out[(size_t)tok * NTt + tid] = lg[tid];
    __syncthreads();
    if (tid < HDd) {
        float la = 0.f;
        for (int t = 0; t < NTt; t++) la += probs[t] * temb[(size_t)t * HDd + tid];
        latent[tid] = la;
    }
    __syncthreads();
    if (tid < HDd) {
        float a = bqt[tid], c = bkt[tid];
        for (int e = 0; e < HDd; e++) {
            float lv = latent[e];
            a += lv * Wqt[(size_t)tid * HDd + e];
            c += lv * Wkt[(size_t)tid * HDd + e];
        }
        qt[(size_t)tok * HDd + tid] = a;
        kt[(size_t)tok * HDd + tid] = c;
    }
}

// ---------------- qtW[b,h,q,e] = sum_d qt[b,q,d] * W_bil[h,d,e] ----------------
__global__ __launch_bounds__(256)
void qtw_kernel(const float* __restrict__ qt, const float* __restrict__ Wb,
                float* __restrict__ qtW)
{
    __shared__ float Qs[64][65];
    __shared__ float Ws[64][65];
    int h = blockIdx.y;
    int t0 = blockIdx.x * 64;
    int tid = threadIdx.x;
    for (int i = tid; i < 4096; i += 256) {
        int r = i >> 6, c = i & 63;
        Qs[r][c] = qt[(size_t)(t0 + r) * HDd + c];
        Ws[r][c] = Wb[(size_t)h * 4096 + i];   // [d][e]
    }
    __syncthreads();
    int tx = tid & 15, ty = tid >> 4;
    float acc[4][4];
#pragma unroll
    for (int i = 0; i < 4; i++)
#pragma unroll
        for (int j = 0; j < 4; j++) acc[i][j] = 0.f;
#pragma unroll 4
    for (int d = 0; d < 64; d++) {
        float a[4], b[4];
#pragma unroll
        for (int i = 0; i < 4; i++) a[i] = Qs[ty * 4 + i][d];
#pragma unroll
        for (int j = 0; j < 4; j++) b[j] = Ws[d][tx * 4 + j];
#pragma unroll
        for (int i = 0; i < 4; i++)
#pragma unroll
            for (int j = 0; j < 4; j++) acc[i][j] += a[i] * b[j];
    }
#pragma unroll
    for (int i = 0; i < 4; i++) {
        int tok = t0 + ty * 4 + i;
        int b = tok >> 11;        // /2048
        int qq = tok & 2047;
        float4 o; o.x = acc[i][0]; o.y = acc[i][1]; o.z = acc[i][2]; o.w = acc[i][3];
        *(float4*)(qtW + (((size_t)(b * NHh + h)) * Ss + qq) * HDd + tx * 4) = o;
    }
}

// ---------------- fused attention + unification logits (flash-style) ----------------
#define SMPAD 68
#define ATTN_SMEM ((6*64*SMPAD + 64) * 4)

__global__ __launch_bounds__(256)
void attn_kernel(const float* __restrict__ q, const float* __restrict__ k,
                 const float* __restrict__ v, const float* __restrict__ kt,
                 const float* __restrict__ qtW, const int* __restrict__ mask,
                 float* __restrict__ unif, float* __restrict__ aout)
{
    extern __shared__ float sm[];
    float (*Qs)[SMPAD]   = (float(*)[SMPAD])(sm);
    float (*QWs)[SMPAD]  = (float(*)[SMPAD])(sm + 1 * 64 * SMPAD);
    float (*KsT)[SMPAD]  = (float(*)[SMPAD])(sm + 2 * 64 * SMPAD);  // [d][j]
    float (*KTsT)[SMPAD] = (float(*)[SMPAD])(sm + 3 * 64 * SMPAD);  // [d][j]
    float (*Vs)[SMPAD]   = (float(*)[SMPAD])(sm + 4 * 64 * SMPAD);  // [j][d]
    float (*Ps)[SMPAD]   = (float(*)[SMPAD])(sm + 5 * 64 * SMPAD);  // [r][j]
    int* maskS = (int*)(sm + 6 * 64 * SMPAD);

    int b = blockIdx.z, h = blockIdx.y, q0 = blockIdx.x * 64;
    int tid = threadIdx.x;
    int tx = tid & 15, ty = tid >> 4;
    int ty4 = ty * 4, tx4 = tx * 4;
    const float NEGINF = __int_as_float(0xff800000);

    for (int i = tid; i < 4096; i += 256) {
        int r = i >> 6, d = i & 63;
        Qs[r][d]  = q[((size_t)(b * Ss + q0 + r)) * Hh + h * HDd + d];
        QWs[r][d] = qtW[(((size_t)(b * NHh + h)) * Ss + q0 + r) * HDd + d];
    }

    float m[4], l[4], oacc[4][4];
#pragma unroll
    for (int i = 0; i < 4; i++) {
        m[i] = -1e30f; l[i] = 0.f;
#pragma unroll
        for (int j = 0; j < 4; j++) oacc[i][j] = 0.f;
    }

    for (int k0 = 0; k0 < Ss; k0 += 64) {
        for (int i = tid; i < 4096; i += 256) {
            int r = i >> 6, d = i & 63;
            size_t gi = ((size_t)(b * Ss + k0 + r)) * Hh + h * HDd + d;
            KsT[d][r]  = k[gi];
            Vs[r][d]   = v[gi];
            KTsT[d][r] = kt[((size_t)(b * Ss + k0 + r)) * HDd + d];
        }
        if (tid < 64) maskS[tid] = mask[b * Ss + k0 + tid];
        __syncthreads();

        float sv[4][4], su[4][4];
#pragma unroll
        for (int i = 0; i < 4; i++)
#pragma unroll
            for (int j = 0; j < 4; j++) { sv[i][j] = 0.f; su[i][j] = 0.f; }

#pragma unroll 4
        for (int d = 0; d < 64; d++) {
            float4 kb  = ((const float4*)(KsT[d]))[tx];
            float4 kb2 = ((const float4*)(KTsT[d]))[tx];
#pragma unroll
            for (int i = 0; i < 4; i++) {
                float qa = Qs[ty4 + i][d];
                float qb = QWs[ty4 + i][d];
                sv[i][0] += qa * kb.x;  sv[i][1] += qa * kb.y;
                sv[i][2] += qa * kb.z;  sv[i][3] += qa * kb.w;
                su[i][0] += qb * kb2.x; su[i][1] += qb * kb2.y;
                su[i][2] += qb * kb2.z; su[i][3] += qb * kb2.w;
            }
        }

#pragma unroll
        for (int i = 0; i < 4; i++) {
            float4 uu;
            uu.x = su[i][0] * SCALE; uu.y = su[i][1] * SCALE;
            uu.z = su[i][2] * SCALE; uu.w = su[i][3] * SCALE;
            *(float4*)(unif + (((size_t)(b * NHh + h)) * Ss + q0 + ty4 + i) * Ss + k0 + tx4) = uu;

            float cb[4];
#pragma unroll
            for (int jj = 0; jj < 4; jj++) {
                float u = su[i][jj] * SCALE;
                float sig = __fdividef(1.f, 1.f + __expf(-u));
                float cc = sv[i][jj] * SCALE + __logf(sig + 1e-6f);
                if (maskS[tx4 + jj] == 0) cc = NEGINF;
                cb[jj] = cc;
            }
            float rm = fmaxf(fmaxf(cb[0], cb[1]), fmaxf(cb[2], cb[3]));
            rm = fmaxf(rm, __shfl_xor_sync(0xffffffffu, rm, 1));
            rm = fmaxf(rm, __shfl_xor_sync(0xffffffffu, rm, 2));
            rm = fmaxf(rm, __shfl_xor_sync(0xffffffffu, rm, 4));
            rm = fmaxf(rm, __shfl_xor_sync(0xffffffffu, rm, 8));
            float nm = fmaxf(m[i], rm);
            float corr = __expf(m[i] - nm);
            m[i] = nm;
            l[i] *= corr;
#pragma unroll
            for (int dd = 0; dd < 4; dd++) oacc[i][dd] *= corr;
            float ps = 0.f;
#pragma unroll
            for (int jj = 0; jj < 4; jj++) {
                float p = __expf(cb[jj] - nm);
                ps += p;
                Ps[ty4 + i][tx4 + jj] = p;
            }
            ps += __shfl_xor_sync(0xffffffffu, ps, 1);
            ps += __shfl_xor_sync(0xffffffffu, ps, 2);
            ps += __shfl_xor_sync(0xffffffffu, ps, 4);
            ps += __shfl_xor_sync(0xffffffffu, ps, 8);
            l[i] += ps;
        }
        __syncthreads();

#pragma unroll 4
        for (int j = 0; j < 64; j++) {
            float4 vv = ((const float4*)(Vs[j]))[tx];
#pragma unroll
            for (int i = 0; i < 4; i++) {
                float p = Ps[ty4 + i][j];
                oacc[i][0] += p * vv.x; oacc[i][1] += p * vv.y;
                oacc[i][2] += p * vv.z; oacc[i][3] += p * vv.w;
            }
        }
        __syncthreads();
    }

#pragma unroll
    for (int i = 0; i < 4; i++) {
        float inv = 1.0f / l[i];
        float4 o;
        o.x = oacc[i][0] * inv; o.y = oacc[i][1] * inv;
        o.z = oacc[i][2] * inv; o.w = oacc[i][3] * inv;
        *(float4*)(aout + ((size_t)(b * Ss + q0 + ty4 + i)) * Hh + h * HDd + tx4) = o;
    }
}

// ---------------- launch ----------------
extern "C" void kernel_launch(void* const* d_in, const int* in_sizes, int n_in,
                              void* d_out, int out_size)
{
    (void)in_sizes; (void)n_in; (void)out_size;
    const float* x    = (const float*)d_in[0];
    const int*   mask = (const int*)  d_in[1];
    const float* Wq   = (const float*)d_in[2];
    const float* bq   = (const float*)d_in[3];
    const float* Wk   = (const float*)d_in[4];
    const float* bk   = (const float*)d_in[5];
    const float* Wv   = (const float*)d_in[6];
    const float* bv   = (const float*)d_in[7];
    const float* Wo   = (const float*)d_in[8];
    const float* bo   = (const float*)d_in[9];
    const float* Wti  = (const float*)d_in[10];
    const float* bti  = (const float*)d_in[11];
    const float* temb = (const float*)d_in[12];
    const float* Wqt  = (const float*)d_in[13];
    const float* bqt  = (const float*)d_in[14];
    const float* Wkt  = (const float*)d_in[15];
    const float* bkt  = (const float*)d_in[16];
    const float* Wbil = (const float*)d_in[17];

    float* out      = (float*)d_out;
    float* out_y    = out;                                  // [B,S,H]
    float* out_tl   = out + (size_t)TOKS * Hh;              // [B,S,NT]
    float* out_unif = out_tl + (size_t)TOKS * NTt;          // [B,NH,S,S]

    float *q, *k, *v, *qt, *kt, *qtW, *attn;
    cudaGetSymbolAddress((void**)&q,    g_q);
    cudaGetSymbolAddress((void**)&k,    g_k);
    cudaGetSymbolAddress((void**)&v,    g_v);
    cudaGetSymbolAddress((void**)&qt,   g_qt);
    cudaGetSymbolAddress((void**)&kt,   g_kt);
    cudaGetSymbolAddress((void**)&qtW,  g_qtW);
    cudaGetSymbolAddress((void**)&attn, g_attn);

    dim3 gg(Hh / 64, TOKS / 64);
    gemm_nt_bias<<<gg, 256>>>(x, Wq, bq, q, TOKS, Hh, Hh);
    gemm_nt_bias<<<gg, 256>>>(x, Wk, bk, k, TOKS, Hh, Hh);
    gemm_nt_bias<<<gg, 256>>>(x, Wv, bv, v, TOKS, Hh, Hh);

    type_kernel<<<TOKS, 128>>>(x, Wti, bti, temb, Wqt, bqt, Wkt, bkt, out_tl, qt, kt);

    qtw_kernel<<<dim3(TOKS / 64, NHh), 256>>>(qt, Wbil, qtW);

    cudaFuncSetAttribute(attn_kernel, cudaFuncAttributeMaxDynamicSharedMemorySize, ATTN_SMEM);
    attn_kernel<<<dim3(Ss / 64, NHh, Bb), 256, ATTN_SMEM>>>(q, k, v, kt, qtW, mask,
                                                            out_unif, attn);

    gemm_nt_bias<<<gg, 256>>>(attn, Wo, bo, out_y, TOKS, Hh, Hh);
}

// round 3
// speedup vs baseline: 1.3832x; 1.3832x over previous
#include <cuda_runtime.h>
#include <cuda_bf16.h>
#include <cstdint>
#include <cstddef>

#define Bb 2
#define Ss 2048
#define Hh 1024
#define NHh 16
#define HDd 64
#define NTt 5
#define TOKS (Bb*Ss)          /* 4096 */
#define SCALE 0.125f          /* 1/sqrt(64) */

// ---------------- scratch (static device globals; no allocation) ----------------
__device__ float g_q[(size_t)TOKS*Hh];
__device__ float g_k[(size_t)TOKS*Hh];
__device__ float g_v[(size_t)TOKS*Hh];
__device__ float g_qt[(size_t)TOKS*HDd];
__device__ float g_kt[(size_t)TOKS*HDd];
__device__ float g_qtW[(size_t)Bb*NHh*Ss*HDd];
__device__ float g_attn[(size_t)TOKS*Hh];
__device__ __nv_bfloat16 g_xhi[(size_t)TOKS*Hh];
__device__ __nv_bfloat16 g_xlo[(size_t)TOKS*Hh];
__device__ __nv_bfloat16 g_whi[(size_t)4*Hh*Hh];
__device__ __nv_bfloat16 g_wlo[(size_t)4*Hh*Hh];

// ================= low-level helpers (all plain sm_80+ features) =================
__device__ __forceinline__ uint32_t smem_u32(const void* p) {
    uint32_t a;
    asm("{ .reg .u64 t; cvta.to.shared.u64 t, %1; cvt.u32.u64 %0, t; }" : "=r"(a) : "l"(p));
    return a;
}
#define CP_ASYNC16(saddr, gaddr) \
    asm volatile("cp.async.cg.shared.global [%0], [%1], 16;" :: "r"(saddr), "l"(gaddr))
#define CP_COMMIT() asm volatile("cp.async.commit_group;" ::: "memory")
#define CP_WAIT1()  asm volatile("cp.async.wait_group 1;" ::: "memory")
#define CP_WAIT0()  asm volatile("cp.async.wait_group 0;" ::: "memory")
#define LDSM_X4(r0, r1, r2, r3, addr) \
    asm volatile("ldmatrix.sync.aligned.m8n8.x4.shared.b16 {%0,%1,%2,%3}, [%4];" \
        : "=r"(r0), "=r"(r1), "=r"(r2), "=r"(r3) : "r"(addr))
#define MMA16816(c, a, b0, b1) \
    asm volatile("mma.sync.aligned.m16n8k16.row.col.f32.bf16.bf16.f32 " \
        "{%0,%1,%2,%3}, {%4,%5,%6,%7}, {%8,%9}, {%0,%1,%2,%3};" \
        : "+f"((c)[0]), "+f"((c)[1]), "+f"((c)[2]), "+f"((c)[3]) \
        : "r"((a)[0]), "r"((a)[1]), "r"((a)[2]), "r"((a)[3]), "r"(b0), "r"(b1))

// ================= fp32 -> bf16 (hi, lo) split =================
__global__ __launch_bounds__(256)
void cvt_split(const float4* __restrict__ in, __nv_bfloat162* __restrict__ hi,
               __nv_bfloat162* __restrict__ lo, int n4)
{
    int i = blockIdx.x * 256 + threadIdx.x;
    if (i >= n4) return;
    float4 f = in[i];
    __nv_bfloat16 hx = __float2bfloat16(f.x), hy = __float2bfloat16(f.y);
    __nv_bfloat16 hz = __float2bfloat16(f.z), hw = __float2bfloat16(f.w);
    __nv_bfloat16 lx = __float2bfloat16(f.x - __bfloat162float(hx));
    __nv_bfloat16 ly = __float2bfloat16(f.y - __bfloat162float(hy));
    __nv_bfloat16 lz = __float2bfloat16(f.z - __bfloat162float(hz));
    __nv_bfloat16 lw = __float2bfloat16(f.w - __bfloat162float(hw));
    hi[2*i]   = __nv_bfloat162(hx, hy);
    hi[2*i+1] = __nv_bfloat162(hz, hw);
    lo[2*i]   = __nv_bfloat162(lx, ly);
    lo[2*i+1] = __nv_bfloat162(lz, lw);
}

// ================= HMMA bf16-split GEMM: C = A @ W^T + bias =================
// A: [4096,1024] (hi/lo bf16), W: [1024,1024] (hi/lo bf16), C: [4096,1024] fp32.
// CTA tile 128x128, K-chunk 64 (128B rows, SW128 swizzle), double-buffered cp.async.
// 8 warps: warp_row = (wid&1)*64, warp_col = (wid>>1)*32. 3 split terms per mma slot.
#define GN 1024
#define BUF_BYTES 65536       /* Ahi 16K | Alo 16K | Whi 16K | Wlo 16K */
#define OFF_AL 16384
#define OFF_WH 32768
#define OFF_WL 49152
#define GEMM_SMEM (2*BUF_BYTES + 512)

__device__ __forceinline__ void load_chunk_mma(
    uint32_t sbuf, int kc_bytes, int bm, int bn, int tid,
    const __nv_bfloat16* Ahi, const __nv_bfloat16* Alo,
    const __nv_bfloat16* Whi, const __nv_bfloat16* Wlo)
{
#pragma unroll
    for (int i = tid; i < 1024; i += 256) {
        int r = i >> 3, c = i & 7;
        uint32_t sw = (uint32_t)(r * 128) + (uint32_t)((c ^ (r & 7)) << 4);
        size_t goA = ((size_t)(bm + r) << 11) + kc_bytes + (c << 4);
        size_t goW = ((size_t)(bn + r) << 11) + kc_bytes + (c << 4);
        CP_ASYNC16(sbuf + sw,          (const char*)Ahi + goA);
        CP_ASYNC16(sbuf + OFF_AL + sw, (const char*)Alo + goA);
        CP_ASYNC16(sbuf + OFF_WH + sw, (const char*)Whi + goW);
        CP_ASYNC16(sbuf + OFF_WL + sw, (const char*)Wlo + goW);
    }
}

__global__ __launch_bounds__(256)
void gemm_hmma(const __nv_bfloat16* __restrict__ Ahi, const __nv_bfloat16* __restrict__ Alo,
               const __nv_bfloat16* __restrict__ Whi, const __nv_bfloat16* __restrict__ Wlo,
               const float* __restrict__ bias, float* __restrict__ C)
{
    extern __shared__ char sm_[];
    uint32_t sb = smem_u32(sm_);
    float* bias_s = (float*)(sm_ + 2 * BUF_BYTES);
    int tid = threadIdx.x, wid = tid >> 5, lid = tid & 31;
    int bm = blockIdx.y * 128, bn = blockIdx.x * 128;

    if (tid < 128) bias_s[tid] = bias[bn + tid];

    int warp_row = (wid & 1) * 64;
    int warp_col = (wid >> 1) * 32;
    int sub = lid & 7;
    int gA1 = (lid >> 3) & 1;       // A: row +8 selector
    int ca  = (lid >> 4) & 1;       // A: k-chunk16 selector
    int gB2 = (lid >> 4) & 1;       // B: row +8 selector
    int cb  = (lid >> 3) & 1;       // B: k-chunk16 selector
    int swz = sub;                  // row & 7 for both (tiles 16-row aligned)

    // per-fragment smem row bases (relative to buffer start)
    uint32_t aBase[4], bBase[2];
#pragma unroll
    for (int i = 0; i < 4; i++)
        aBase[i] = (uint32_t)((warp_row + i * 16 + gA1 * 8 + sub) * 128);
#pragma unroll
    for (int p = 0; p < 2; p++)
        bBase[p] = (uint32_t)((warp_col + p * 16 + gB2 * 8 + sub) * 128);

    float acc[4][4][4];
#pragma unroll
    for (int i = 0; i < 4; i++)
#pragma unroll
        for (int jn = 0; jn < 4; jn++)
#pragma unroll
            for (int r = 0; r < 4; r++) acc[i][jn][r] = 0.f;

    load_chunk_mma(sb, 0, bm, bn, tid, Ahi, Alo, Whi, Wlo);
    CP_COMMIT();

    for (int c = 0; c < 16; c++) {
        if (c + 1 < 16) {
            load_chunk_mma(sb + ((c + 1) & 1) * BUF_BYTES, (c + 1) * 128, bm, bn, tid,
                           Ahi, Alo, Whi, Wlo);
            CP_COMMIT();
            CP_WAIT1();
        } else {
            CP_WAIT0();
        }
        __syncthreads();

        uint32_t bufoff = sb + (c & 1) * BUF_BYTES;
#pragma unroll
        for (int j = 0; j < 4; j++) {
            uint32_t ah[4][4], al[4][4], bh[2][4], bl[2][4];
#pragma unroll
            for (int i = 0; i < 4; i++) {
                uint32_t ad = bufoff + aBase[i] + (uint32_t)((((2 * j + ca) ^ swz)) << 4);
                LDSM_X4(ah[i][0], ah[i][1], ah[i][2], ah[i][3], ad);
                LDSM_X4(al[i][0], al[i][1], al[i][2], al[i][3], ad + OFF_AL);
            }
#pragma unroll
            for (int p = 0; p < 2; p++) {
                uint32_t bd = bufoff + bBase[p] + (uint32_t)((((2 * j + cb) ^ swz)) << 4);
                LDSM_X4(bh[p][0], bh[p][1], bh[p][2], bh[p][3], bd + OFF_WH);
                LDSM_X4(bl[p][0], bl[p][1], bl[p][2], bl[p][3], bd + OFF_WL);
            }
#pragma unroll
            for (int i = 0; i < 4; i++) {
#pragma unroll
                for (int jn = 0; jn < 4; jn++) {
                    int p = jn >> 1, q = (jn & 1) * 2;
                    MMA16816(acc[i][jn], ah[i], bh[p][q], bh[p][q + 1]);
                    MMA16816(acc[i][jn], ah[i], bl[p][q], bl[p][q + 1]);
                    MMA16816(acc[i][jn], al[i], bh[p][q], bh[p][q + 1]);
                }
            }
        }
        __syncthreads();
    }

    // epilogue: c-frag lane mapping row=l>>2 (+8), col=(l&3)*2 (+1)
    int lr = lid >> 2, lc = (lid & 3) * 2;
#pragma unroll
    for (int i = 0; i < 4; i++) {
#pragma unroll
        for (int jn = 0; jn < 4; jn++) {
            int row = bm + warp_row + i * 16 + lr;
            int colL = warp_col + jn * 8 + lc;
            int col = bn + colL;
            float b0 = bias_s[colL], b1 = bias_s[colL + 1];
            float2 v0 = make_float2(acc[i][jn][0] + b0, acc[i][jn][1] + b1);
            float2 v1 = make_float2(acc[i][jn][2] + b0, acc[i][jn][3] + b1);
            *(float2*)(C + (size_t)row * GN + col)       = v0;
            *(float2*)(C + (size_t)(row + 8) * GN + col) = v1;
        }
    }
}

// ---------------- type inference v2: warp-per-token ----------------
__global__ __launch_bounds__(512)
void type_kernel2(const float* __restrict__ x, const float* __restrict__ Wti,
                  const float* __restrict__ bti, const float* __restrict__ temb,
                  const float* __restrict__ Wqt, const float* __restrict__ bqt,
                  const float* __restrict__ Wkt, const float* __restrict__ bkt,
                  float* __restrict__ tl_out, float* __restrict__ qt, float* __restrict__ kt)
{
    __shared__ float sWti[NTt * Hh];
    __shared__ float stemb[NTt * HDd];
    __shared__ float slat[16][HDd];
    int tid = threadIdx.x, wid = tid >> 5, lid = tid & 31;
    for (int i = tid; i < NTt * Hh; i += 512) sWti[i] = Wti[i];
    for (int i = tid; i < NTt * HDd; i += 512) stemb[i] = temb[i];
    __syncthreads();

    int tok = blockIdx.x * 16 + wid;
    const float* xr = x + (size_t)tok * Hh;
    float xv[32];
#pragma unroll
    for (int j = 0; j < 32; j++) xv[j] = xr[lid + 32 * j];

    float lg[NTt];
#pragma unroll
    for (int t = 0; t < NTt; t++) {
        float s = 0.f;
#pragma unroll
        for (int j = 0; j < 32; j++) s += xv[j] * sWti[t * Hh + lid + 32 * j];
        s += __shfl_xor_sync(0xffffffffu, s, 16);
        s += __shfl_xor_sync(0xffffffffu, s, 8);
        s += __shfl_xor_sync(0xffffffffu, s, 4);
        s += __shfl_xor_sync(0xffffffffu, s, 2);
        s += __shfl_xor_sync(0xffffffffu, s, 1);
        lg[t] = s + bti[t];
    }
    if (lid == 0) {
        float* tl = tl_out + (size_t)tok * NTt;
#pragma unroll
        for (int t = 0; t < NTt; t++) tl[t] = lg[t];
    }
    float mx = lg[0];
#pragma unroll
    for (int t = 1; t < NTt; t++) mx = fmaxf(mx, lg[t]);
    float e[NTt], se = 0.f;
#pragma unroll
    for (int t = 0; t < NTt; t++) { e[t] = expf(lg[t] - mx); se += e[t]; }
    float inv = 1.f / se;

    float la0 = 0.f, la1 = 0.f;
#pragma unroll
    for (int t = 0; t < NTt; t++) {
        float p = e[t] * inv;
        la0 += p * stemb[t * HDd + lid];
        la1 += p * stemb[t * HDd + lid + 32];
    }
    slat[wid][lid] = la0;
    slat[wid][lid + 32] = la1;
    __syncwarp();

#pragma unroll
    for (int rep = 0; rep < 2; rep++) {
        int d = lid + rep * 32;
        float a = bqt[d], c = bkt[d];
        const float* wq = Wqt + (size_t)d * HDd;
        const float* wk = Wkt + (size_t)d * HDd;
#pragma unroll
        for (int e2 = 0; e2 < HDd; e2++) {
            float lv = slat[wid][e2];
            a += lv * wq[e2];
            c += lv * wk[e2];
        }
        qt[(size_t)tok * HDd + d] = a;
        kt[(size_t)tok * HDd + d] = c;
    }
}

// ---------------- qtW[b,h,q,e] = sum_d qt[b,q,d] * W_bil[h,d,e] ----------------
__global__ __launch_bounds__(256)
void qtw_kernel(const float* __restrict__ qt, const float* __restrict__ Wb,
                float* __restrict__ qtW)
{
    __shared__ float Qs[64][65];
    __shared__ float Ws[64][65];
    int h = blockIdx.y;
    int t0 = blockIdx.x * 64;
    int tid = threadIdx.x;
    for (int i = tid; i < 4096; i += 256) {
        int r = i >> 6, c = i & 63;
        Qs[r][c] = qt[(size_t)(t0 + r) * HDd + c];
        Ws[r][c] = Wb[(size_t)h * 4096 + i];
    }
    __syncthreads();
    int tx = tid & 15, ty = tid >> 4;
    float acc[4][4];
#pragma unroll
    for (int i = 0; i < 4; i++)
#pragma unroll
        for (int j = 0; j < 4; j++) acc[i][j] = 0.f;
#pragma unroll 4
    for (int d = 0; d < 64; d++) {
        float a[4], b[4];
#pragma unroll
        for (int i = 0; i < 4; i++) a[i] = Qs[ty * 4 + i][d];
#pragma unroll
        for (int j = 0; j < 4; j++) b[j] = Ws[d][tx * 4 + j];
#pragma unroll
        for (int i = 0; i < 4; i++)
#pragma unroll
            for (int j = 0; j < 4; j++) acc[i][j] += a[i] * b[j];
    }
#pragma unroll
    for (int i = 0; i < 4; i++) {
        int tok = t0 + ty * 4 + i;
        int b = tok >> 11;
        int qq = tok & 2047;
        float4 o; o.x = acc[i][0]; o.y = acc[i][1]; o.z = acc[i][2]; o.w = acc[i][3];
        *(float4*)(qtW + (((size_t)(b * NHh + h)) * Ss + qq) * HDd + tx * 4) = o;
    }
}

// ---------------- fused attention + unification logits (flash-style) ----------------
#define SMPAD 68
#define ATTN_SMEM ((6*64*SMPAD + 64) * 4)

__global__ __launch_bounds__(256)
void attn_kernel(const float* __restrict__ q, const float* __restrict__ k,
                 const float* __restrict__ v, const float* __restrict__ kt,
                 const float* __restrict__ qtW, const int* __restrict__ mask,
                 float* __restrict__ unif, float* __restrict__ aout)
{
    extern __shared__ float sm[];
    float (*Qs)[SMPAD]   = (float(*)[SMPAD])(sm);
    float (*QWs)[SMPAD]  = (float(*)[SMPAD])(sm + 1 * 64 * SMPAD);
    float (*KsT)[SMPAD]  = (float(*)[SMPAD])(sm + 2 * 64 * SMPAD);
    float (*KTsT)[SMPAD] = (float(*)[SMPAD])(sm + 3 * 64 * SMPAD);
    float (*Vs)[SMPAD]   = (float(*)[SMPAD])(sm + 4 * 64 * SMPAD);
    float (*Ps)[SMPAD]   = (float(*)[SMPAD])(sm + 5 * 64 * SMPAD);
    int* maskS = (int*)(sm + 6 * 64 * SMPAD);

    int b = blockIdx.z, h = blockIdx.y, q0 = blockIdx.x * 64;
    int tid = threadIdx.x;
    int tx = tid & 15, ty = tid >> 4;
    int ty4 = ty * 4, tx4 = tx * 4;
    const float NEGINF = __int_as_float(0xff800000);

    for (int i = tid; i < 4096; i += 256) {
        int r = i >> 6, d = i & 63;
        Qs[r][d]  = q[((size_t)(b * Ss + q0 + r)) * Hh + h * HDd + d];
        QWs[r][d] = qtW[(((size_t)(b * NHh + h)) * Ss + q0 + r) * HDd + d];
    }

    float m[4], l[4], oacc[4][4];
#pragma unroll
    for (int i = 0; i < 4; i++) {
        m[i] = -1e30f; l[i] = 0.f;
#pragma unroll
        for (int j = 0; j < 4; j++) oacc[i][j] = 0.f;
    }

    for (int k0 = 0; k0 < Ss; k0 += 64) {
        for (int i = tid; i < 4096; i += 256) {
            int r = i >> 6, d = i & 63;
            size_t gi = ((size_t)(b * Ss + k0 + r)) * Hh + h * HDd + d;
            KsT[d][r]  = k[gi];
            Vs[r][d]   = v[gi];
            KTsT[d][r] = kt[((size_t)(b * Ss + k0 + r)) * HDd + d];
        }
        if (tid < 64) maskS[tid] = mask[b * Ss + k0 + tid];
        __syncthreads();

        float sv[4][4], su[4][4];
#pragma unroll
        for (int i = 0; i < 4; i++)
#pragma unroll
            for (int j = 0; j < 4; j++) { sv[i][j] = 0.f; su[i][j] = 0.f; }

#pragma unroll 4
        for (int d = 0; d < 64; d++) {
            float4 kb  = ((const float4*)(KsT[d]))[tx];
            float4 kb2 = ((const float4*)(KTsT[d]))[tx];
#pragma unroll
            for (int i = 0; i < 4; i++) {
                float qa = Qs[ty4 + i][d];
                float qb = QWs[ty4 + i][d];
                sv[i][0] += qa * kb.x;  sv[i][1] += qa * kb.y;
                sv[i][2] += qa * kb.z;  sv[i][3] += qa * kb.w;
                su[i][0] += qb * kb2.x; su[i][1] += qb * kb2.y;
                su[i][2] += qb * kb2.z; su[i][3] += qb * kb2.w;
            }
        }

#pragma unroll
        for (int i = 0; i < 4; i++) {
            float4 uu;
            uu.x = su[i][0] * SCALE; uu.y = su[i][1] * SCALE;
            uu.z = su[i][2] * SCALE; uu.w = su[i][3] * SCALE;
            *(float4*)(unif + (((size_t)(b * NHh + h)) * Ss + q0 + ty4 + i) * Ss + k0 + tx4) = uu;

            float cb[4];
#pragma unroll
            for (int jj = 0; jj < 4; jj++) {
                float u = su[i][jj] * SCALE;
                float sig = __fdividef(1.f, 1.f + __expf(-u));
                float cc = sv[i][jj] * SCALE + __logf(sig + 1e-6f);
                if (maskS[tx4 + jj] == 0) cc = NEGINF;
                cb[jj] = cc;
            }
            float rm = fmaxf(fmaxf(cb[0], cb[1]), fmaxf(cb[2], cb[3]));
            rm = fmaxf(rm, __shfl_xor_sync(0xffffffffu, rm, 1));
            rm = fmaxf(rm, __shfl_xor_sync(0xffffffffu, rm, 2));
            rm = fmaxf(rm, __shfl_xor_sync(0xffffffffu, rm, 4));
            rm = fmaxf(rm, __shfl_xor_sync(0xffffffffu, rm, 8));
            float nm = fmaxf(m[i], rm);
            float corr = __expf(m[i] - nm);
            m[i] = nm;
            l[i] *= corr;
#pragma unroll
            for (int dd = 0; dd < 4; dd++) oacc[i][dd] *= corr;
            float ps = 0.f;
#pragma unroll
            for (int jj = 0; jj < 4; jj++) {
                float p = __expf(cb[jj] - nm);
                ps += p;
                Ps[ty4 + i][tx4 + jj] = p;
            }
            ps += __shfl_xor_sync(0xffffffffu, ps, 1);
            ps += __shfl_xor_sync(0xffffffffu, ps, 2);
            ps += __shfl_xor_sync(0xffffffffu, ps, 4);
            ps += __shfl_xor_sync(0xffffffffu, ps, 8);
            l[i] += ps;
        }
        __syncthreads();

#pragma unroll 4
        for (int j = 0; j < 64; j++) {
            float4 vv = ((const float4*)(Vs[j]))[tx];
#pragma unroll
            for (int i = 0; i < 4; i++) {
                float p = Ps[ty4 + i][j];
                oacc[i][0] += p * vv.x; oacc[i][1] += p * vv.y;
                oacc[i][2] += p * vv.z; oacc[i][3] += p * vv.w;
            }
        }
        __syncthreads();
    }

#pragma unroll
    for (int i = 0; i < 4; i++) {
        float inv = 1.0f / l[i];
        float4 o;
        o.x = oacc[i][0] * inv; o.y = oacc[i][1] * inv;
        o.z = oacc[i][2] * inv; o.w = oacc[i][3] * inv;
        *(float4*)(aout + ((size_t)(b * Ss + q0 + ty4 + i)) * Hh + h * HDd + tx4) = o;
    }
}

// ---------------- launch ----------------
extern "C" void kernel_launch(void* const* d_in, const int* in_sizes, int n_in,
                              void* d_out, int out_size)
{
    (void)in_sizes; (void)n_in; (void)out_size;
    const float* x    = (const float*)d_in[0];
    const int*   mask = (const int*)  d_in[1];
    const float* Wq   = (const float*)d_in[2];
    const float* bq   = (const float*)d_in[3];
    const float* Wk   = (const float*)d_in[4];
    const float* bk   = (const float*)d_in[5];
    const float* Wv   = (const float*)d_in[6];
    const float* bv   = (const float*)d_in[7];
    const float* Wo   = (const float*)d_in[8];
    const float* bo   = (const float*)d_in[9];
    const float* Wti  = (const float*)d_in[10];
    const float* bti  = (const float*)d_in[11];
    const float* temb = (const float*)d_in[12];
    const float* Wqt  = (const float*)d_in[13];
    const float* bqt  = (const float*)d_in[14];
    const float* Wkt  = (const float*)d_in[15];
    const float* bkt  = (const float*)d_in[16];
    const float* Wbil = (const float*)d_in[17];

    float* out      = (float*)d_out;
    float* out_y    = out;
    float* out_tl   = out + (size_t)TOKS * Hh;
    float* out_unif = out_tl + (size_t)TOKS * NTt;

    float *q, *k, *v, *qt, *kt, *qtW, *attn;
    __nv_bfloat16 *xhi, *xlo, *whi, *wlo;
    cudaGetSymbolAddress((void**)&q,    g_q);
    cudaGetSymbolAddress((void**)&k,    g_k);
    cudaGetSymbolAddress((void**)&v,    g_v);
    cudaGetSymbolAddress((void**)&qt,   g_qt);
    cudaGetSymbolAddress((void**)&kt,   g_kt);
    cudaGetSymbolAddress((void**)&qtW,  g_qtW);
    cudaGetSymbolAddress((void**)&attn, g_attn);
    cudaGetSymbolAddress((void**)&xhi,  g_xhi);
    cudaGetSymbolAddress((void**)&xlo,  g_xlo);
    cudaGetSymbolAddress((void**)&whi,  g_whi);
    cudaGetSymbolAddress((void**)&wlo,  g_wlo);

    const size_t WSZ = (size_t)Hh * Hh;
    cvt_split<<<(TOKS * Hh / 4 + 255) / 256, 256>>>((const float4*)x,
        (__nv_bfloat162*)xhi, (__nv_bfloat162*)xlo, TOKS * Hh / 4);
    cvt_split<<<(WSZ / 4 + 255) / 256, 256>>>((const float4*)Wq,
        (__nv_bfloat162*)(whi + 0 * WSZ), (__nv_bfloat162*)(wlo + 0 * WSZ), WSZ / 4);
    cvt_split<<<(WSZ / 4 + 255) / 256, 256>>>((const float4*)Wk,
        (__nv_bfloat162*)(whi + 1 * WSZ), (__nv_bfloat162*)(wlo + 1 * WSZ), WSZ / 4);
    cvt_split<<<(WSZ / 4 + 255) / 256, 256>>>((const float4*)Wv,
        (__nv_bfloat162*)(whi + 2 * WSZ), (__nv_bfloat162*)(wlo + 2 * WSZ), WSZ / 4);
    cvt_split<<<(WSZ / 4 + 255) / 256, 256>>>((const float4*)Wo,
        (__nv_bfloat162*)(whi + 3 * WSZ), (__nv_bfloat162*)(wlo + 3 * WSZ), WSZ / 4);

    cudaFuncSetAttribute(gemm_hmma, cudaFuncAttributeMaxDynamicSharedMemorySize, GEMM_SMEM);
    dim3 gg(GN / 128, TOKS / 128);
    gemm_hmma<<<gg, 256, GEMM_SMEM>>>(xhi, xlo, whi + 0 * WSZ, wlo + 0 * WSZ, bq, q);
    gemm_hmma<<<gg, 256, GEMM_SMEM>>>(xhi, xlo, whi + 1 * WSZ, wlo + 1 * WSZ, bk, k);
    gemm_hmma<<<gg, 256, GEMM_SMEM>>>(xhi, xlo, whi + 2 * WSZ, wlo + 2 * WSZ, bv, v);

    type_kernel2<<<TOKS / 16, 512>>>(x, Wti, bti, temb, Wqt, bqt, Wkt, bkt, out_tl, qt, kt);

    qtw_kernel<<<dim3(TOKS / 64, NHh), 256>>>(qt, Wbil, qtW);

    cudaFuncSetAttribute(attn_kernel, cudaFuncAttributeMaxDynamicSharedMemorySize, ATTN_SMEM);
    attn_kernel<<<dim3(Ss / 64, NHh, Bb), 256, ATTN_SMEM>>>(q, k, v, kt, qtW, mask,
                                                            out_unif, attn);

    cvt_split<<<(TOKS * Hh / 4 + 255) / 256, 256>>>((const float4*)attn,
        (__nv_bfloat162*)xhi, (__nv_bfloat162*)xlo, TOKS * Hh / 4);
    gemm_hmma<<<gg, 256, GEMM_SMEM>>>(xhi, xlo, whi + 3 * WSZ, wlo + 3 * WSZ, bo, out_y);
}

// round 4
// speedup vs baseline: 2.9984x; 2.1677x over previous
#include <cuda_runtime.h>
#include <cuda_bf16.h>
#include <cstdint>
#include <cstddef>

#define Bb 2
#define Ss 2048
#define Hh 1024
#define NHh 16
#define HDd 64
#define NTt 5
#define TOKS (Bb*Ss)          /* 4096 */
#define SCALE 0.125f          /* 1/sqrt(64) */

// ---------------- scratch (static device globals; no allocation) ----------------
__device__ float g_qt[(size_t)TOKS*HDd];
__device__ __nv_bfloat16 g_xhi[(size_t)TOKS*Hh];
__device__ __nv_bfloat16 g_xlo[(size_t)TOKS*Hh];
__device__ __nv_bfloat16 g_whi[(size_t)4*Hh*Hh];
__device__ __nv_bfloat16 g_wlo[(size_t)4*Hh*Hh];
__device__ __nv_bfloat16 g_qhi[(size_t)TOKS*Hh];
__device__ __nv_bfloat16 g_qlo[(size_t)TOKS*Hh];
__device__ __nv_bfloat16 g_khi[(size_t)TOKS*Hh];
__device__ __nv_bfloat16 g_klo[(size_t)TOKS*Hh];
__device__ __nv_bfloat16 g_vhi[(size_t)TOKS*Hh];
__device__ __nv_bfloat16 g_vlo[(size_t)TOKS*Hh];
__device__ __nv_bfloat16 g_kthi[(size_t)TOKS*HDd];
__device__ __nv_bfloat16 g_ktlo[(size_t)TOKS*HDd];
__device__ __nv_bfloat16 g_qwhi[(size_t)Bb*NHh*Ss*HDd];
__device__ __nv_bfloat16 g_qwlo[(size_t)Bb*NHh*Ss*HDd];

// ================= low-level helpers (all plain sm_80+ features) =================
__device__ __forceinline__ uint32_t smem_u32(const void* p) {
    uint32_t a;
    asm("{ .reg .u64 t; cvta.to.shared.u64 t, %1; cvt.u32.u64 %0, t; }" : "=r"(a) : "l"(p));
    return a;
}
#define CP_ASYNC16(saddr, gaddr) \
    asm volatile("cp.async.cg.shared.global [%0], [%1], 16;" :: "r"(saddr), "l"(gaddr))
#define CP_COMMIT() asm volatile("cp.async.commit_group;" ::: "memory")
#define CP_WAIT1()  asm volatile("cp.async.wait_group 1;" ::: "memory")
#define CP_WAIT0()  asm volatile("cp.async.wait_group 0;" ::: "memory")
#define LDSM_X4(r0, r1, r2, r3, addr) \
    asm volatile("ldmatrix.sync.aligned.m8n8.x4.shared.b16 {%0,%1,%2,%3}, [%4];" \
        : "=r"(r0), "=r"(r1), "=r"(r2), "=r"(r3) : "r"(addr))
#define LDSM_X4_T(r0, r1, r2, r3, addr) \
    asm volatile("ldmatrix.sync.aligned.m8n8.x4.trans.shared.b16 {%0,%1,%2,%3}, [%4];" \
        : "=r"(r0), "=r"(r1), "=r"(r2), "=r"(r3) : "r"(addr))
#define MMA16816(c, a, b0, b1) \
    asm volatile("mma.sync.aligned.m16n8k16.row.col.f32.bf16.bf16.f32 " \
        "{%0,%1,%2,%3}, {%4,%5,%6,%7}, {%8,%9}, {%0,%1,%2,%3};" \
        : "+f"((c)[0]), "+f"((c)[1]), "+f"((c)[2]), "+f"((c)[3]) \
        : "r"((a)[0]), "r"((a)[1]), "r"((a)[2]), "r"((a)[3]), "r"(b0), "r"(b1))

__device__ __forceinline__ void split2(float x, float y, uint32_t& hi, uint32_t& lo) {
    __nv_bfloat16 hx = __float2bfloat16(x), hy = __float2bfloat16(y);
    __nv_bfloat16 lx = __float2bfloat16(x - __bfloat162float(hx));
    __nv_bfloat16 ly = __float2bfloat16(y - __bfloat162float(hy));
    __nv_bfloat162 h2(hx, hy), l2(lx, ly);
    hi = *(uint32_t*)&h2; lo = *(uint32_t*)&l2;
}

// ================= fp32 -> bf16 (hi, lo) split =================
__global__ __launch_bounds__(256)
void cvt_split(const float4* __restrict__ in, __nv_bfloat162* __restrict__ hi,
               __nv_bfloat162* __restrict__ lo, int n4)
{
    int i = blockIdx.x * 256 + threadIdx.x;
    if (i >= n4) return;
    float4 f = in[i];
    uint32_t h0, l0, h1, l1;
    split2(f.x, f.y, h0, l0);
    split2(f.z, f.w, h1, l1);
    ((uint32_t*)hi)[2*i]   = h0; ((uint32_t*)hi)[2*i+1] = h1;
    ((uint32_t*)lo)[2*i]   = l0; ((uint32_t*)lo)[2*i+1] = l1;
}

// ================= HMMA bf16-split GEMM: C = A @ W^T + bias =================
#define GN 1024
#define BUF_BYTES 65536
#define OFF_AL 16384
#define OFF_WH 32768
#define OFF_WL 49152
#define GEMM_SMEM (2*BUF_BYTES + 512)

__device__ __forceinline__ void load_chunk_mma(
    uint32_t sbuf, int kc_bytes, int bm, int bn, int tid,
    const __nv_bfloat16* Ahi, const __nv_bfloat16* Alo,
    const __nv_bfloat16* Whi, const __nv_bfloat16* Wlo)
{
#pragma unroll
    for (int i = tid; i < 1024; i += 256) {
        int r = i >> 3, c = i & 7;
        uint32_t sw = (uint32_t)(r * 128) + (uint32_t)((c ^ (r & 7)) << 4);
        size_t goA = ((size_t)(bm + r) << 11) + kc_bytes + (c << 4);
        size_t goW = ((size_t)(bn + r) << 11) + kc_bytes + (c << 4);
        CP_ASYNC16(sbuf + sw,          (const char*)Ahi + goA);
        CP_ASYNC16(sbuf + OFF_AL + sw, (const char*)Alo + goA);
        CP_ASYNC16(sbuf + OFF_WH + sw, (const char*)Whi + goW);
        CP_ASYNC16(sbuf + OFF_WL + sw, (const char*)Wlo + goW);
    }
}

__global__ __launch_bounds__(256)
void gemm_hmma(const __nv_bfloat16* __restrict__ Ahi, const __nv_bfloat16* __restrict__ Alo,
               const __nv_bfloat16* __restrict__ Whi, const __nv_bfloat16* __restrict__ Wlo,
               const float* __restrict__ bias, float* __restrict__ Cf,
               __nv_bfloat16* __restrict__ Chi, __nv_bfloat16* __restrict__ Clo)
{
    extern __shared__ char sm_[];
    uint32_t sb = smem_u32(sm_);
    float* bias_s = (float*)(sm_ + 2 * BUF_BYTES);
    int tid = threadIdx.x, wid = tid >> 5, lid = tid & 31;
    int bm = blockIdx.y * 128, bn = blockIdx.x * 128;

    if (tid < 128) bias_s[tid] = bias[bn + tid];

    int warp_row = (wid & 1) * 64;
    int warp_col = (wid >> 1) * 32;
    int sub = lid & 7;
    int gA1 = (lid >> 3) & 1;
    int ca  = (lid >> 4) & 1;
    int gB2 = (lid >> 4) & 1;
    int cb  = (lid >> 3) & 1;
    int swz = sub;

    uint32_t aBase[4], bBase[2];
#pragma unroll
    for (int i = 0; i < 4; i++)
        aBase[i] = (uint32_t)((warp_row + i * 16 + gA1 * 8 + sub) * 128);
#pragma unroll
    for (int p = 0; p < 2; p++)
        bBase[p] = (uint32_t)((warp_col + p * 16 + gB2 * 8 + sub) * 128);

    float acc[4][4][4];
#pragma unroll
    for (int i = 0; i < 4; i++)
#pragma unroll
        for (int jn = 0; jn < 4; jn++)
#pragma unroll
            for (int r = 0; r < 4; r++) acc[i][jn][r] = 0.f;

    load_chunk_mma(sb, 0, bm, bn, tid, Ahi, Alo, Whi, Wlo);
    CP_COMMIT();

    for (int c = 0; c < 16; c++) {
        if (c + 1 < 16) {
            load_chunk_mma(sb + ((c + 1) & 1) * BUF_BYTES, (c + 1) * 128, bm, bn, tid,
                           Ahi, Alo, Whi, Wlo);
            CP_COMMIT();
            CP_WAIT1();
        } else {
            CP_WAIT0();
        }
        __syncthreads();

        uint32_t bufoff = sb + (c & 1) * BUF_BYTES;
#pragma unroll
        for (int j = 0; j < 4; j++) {
            uint32_t ah[4][4], al[4][4], bh[2][4], bl[2][4];
#pragma unroll
            for (int i = 0; i < 4; i++) {
                uint32_t ad = bufoff + aBase[i] + (uint32_t)((((2 * j + ca) ^ swz)) << 4);
                LDSM_X4(ah[i][0], ah[i][1], ah[i][2], ah[i][3], ad);
                LDSM_X4(al[i][0], al[i][1], al[i][2], al[i][3], ad + OFF_AL);
            }
#pragma unroll
            for (int p = 0; p < 2; p++) {
                uint32_t bd = bufoff + bBase[p] + (uint32_t)((((2 * j + cb) ^ swz)) << 4);
                LDSM_X4(bh[p][0], bh[p][1], bh[p][2], bh[p][3], bd + OFF_WH);
                LDSM_X4(bl[p][0], bl[p][1], bl[p][2], bl[p][3], bd + OFF_WL);
            }
#pragma unroll
            for (int i = 0; i < 4; i++) {
#pragma unroll
                for (int jn = 0; jn < 4; jn++) {
                    int p = jn >> 1, q = (jn & 1) * 2;
                    MMA16816(acc[i][jn], ah[i], bh[p][q], bh[p][q + 1]);
                    MMA16816(acc[i][jn], ah[i], bl[p][q], bl[p][q + 1]);
                    MMA16816(acc[i][jn], al[i], bh[p][q], bh[p][q + 1]);
                }
            }
        }
        __syncthreads();
    }

    int lr = lid >> 2, lc = (lid & 3) * 2;
#pragma unroll
    for (int i = 0; i < 4; i++) {
#pragma unroll
        for (int jn = 0; jn < 4; jn++) {
            int row = bm + warp_row + i * 16 + lr;
            int colL = warp_col + jn * 8 + lc;
            int col = bn + colL;
            float b0 = bias_s[colL], b1 = bias_s[colL + 1];
            float v00 = acc[i][jn][0] + b0, v01 = acc[i][jn][1] + b1;
            float v10 = acc[i][jn][2] + b0, v11 = acc[i][jn][3] + b1;
            if (Cf) {
                *(float2*)(Cf + (size_t)row * GN + col)       = make_float2(v00, v01);
                *(float2*)(Cf + (size_t)(row + 8) * GN + col) = make_float2(v10, v11);
            }
            if (Chi) {
                uint32_t h0, l0, h1, l1;
                split2(v00, v01, h0, l0);
                split2(v10, v11, h1, l1);
                *(uint32_t*)(Chi + (size_t)row * GN + col)       = h0;
                *(uint32_t*)(Clo + (size_t)row * GN + col)       = l0;
                *(uint32_t*)(Chi + (size_t)(row + 8) * GN + col) = h1;
                *(uint32_t*)(Clo + (size_t)(row + 8) * GN + col) = l1;
            }
        }
    }
}

// ---------------- type inference: warp-per-token ----------------
__global__ __launch_bounds__(512)
void type_kernel2(const float* __restrict__ x, const float* __restrict__ Wti,
                  const float* __restrict__ bti, const float* __restrict__ temb,
                  const float* __restrict__ Wqt, const float* __restrict__ bqt,
                  const float* __restrict__ Wkt, const float* __restrict__ bkt,
                  float* __restrict__ tl_out, float* __restrict__ qt,
                  __nv_bfloat16* __restrict__ kthi, __nv_bfloat16* __restrict__ ktlo)
{
    __shared__ float sWti[NTt * Hh];
    __shared__ float stemb[NTt * HDd];
    __shared__ float slat[16][HDd];
    int tid = threadIdx.x, wid = tid >> 5, lid = tid & 31;
    for (int i = tid; i < NTt * Hh; i += 512) sWti[i] = Wti[i];
    for (int i = tid; i < NTt * HDd; i += 512) stemb[i] = temb[i];
    __syncthreads();

    int tok = blockIdx.x * 16 + wid;
    const float* xr = x + (size_t)tok * Hh;
    float xv[32];
#pragma unroll
    for (int j = 0; j < 32; j++) xv[j] = xr[lid + 32 * j];

    float lg[NTt];
#pragma unroll
    for (int t = 0; t < NTt; t++) {
        float s = 0.f;
#pragma unroll
        for (int j = 0; j < 32; j++) s += xv[j] * sWti[t * Hh + lid + 32 * j];
        s += __shfl_xor_sync(0xffffffffu, s, 16);
        s += __shfl_xor_sync(0xffffffffu, s, 8);
        s += __shfl_xor_sync(0xffffffffu, s, 4);
        s += __shfl_xor_sync(0xffffffffu, s, 2);
        s += __shfl_xor_sync(0xffffffffu, s, 1);
        lg[t] = s + bti[t];
    }
    if (lid == 0) {
        float* tl = tl_out + (size_t)tok * NTt;
#pragma unroll
        for (int t = 0; t < NTt; t++) tl[t] = lg[t];
    }
    float mx = lg[0];
#pragma unroll
    for (int t = 1; t < NTt; t++) mx = fmaxf(mx, lg[t]);
    float e[NTt], se = 0.f;
#pragma unroll
    for (int t = 0; t < NTt; t++) { e[t] = expf(lg[t] - mx); se += e[t]; }
    float inv = 1.f / se;

    float la0 = 0.f, la1 = 0.f;
#pragma unroll
    for (int t = 0; t < NTt; t++) {
        float p = e[t] * inv;
        la0 += p * stemb[t * HDd + lid];
        la1 += p * stemb[t * HDd + lid + 32];
    }
    slat[wid][lid] = la0;
    slat[wid][lid + 32] = la1;
    __syncwarp();

#pragma unroll
    for (int rep = 0; rep < 2; rep++) {
        int d = lid + rep * 32;
        float a = bqt[d], c = bkt[d];
        const float* wq = Wqt + (size_t)d * HDd;
        const float* wk = Wkt + (size_t)d * HDd;
#pragma unroll
        for (int e2 = 0; e2 < HDd; e2++) {
            float lv = slat[wid][e2];
            a += lv * wq[e2];
            c += lv * wk[e2];
        }
        qt[(size_t)tok * HDd + d] = a;
        __nv_bfloat16 hc = __float2bfloat16(c);
        kthi[(size_t)tok * HDd + d] = hc;
        ktlo[(size_t)tok * HDd + d] = __float2bfloat16(c - __bfloat162float(hc));
    }
}

// ---------------- qtW[b,h,q,e] = sum_d qt[b,q,d] * W_bil[h,d,e] (bf16 split out) ----------------
__global__ __launch_bounds__(256)
void qtw_kernel(const float* __restrict__ qt, const float* __restrict__ Wb,
                __nv_bfloat16* __restrict__ qwhi, __nv_bfloat16* __restrict__ qwlo)
{
    __shared__ float Qs[64][65];
    __shared__ float Ws[64][65];
    int h = blockIdx.y;
    int t0 = blockIdx.x * 64;
    int tid = threadIdx.x;
    for (int i = tid; i < 4096; i += 256) {
        int r = i >> 6, c = i & 63;
        Qs[r][c] = qt[(size_t)(t0 + r) * HDd + c];
        Ws[r][c] = Wb[(size_t)h * 4096 + i];
    }
    __syncthreads();
    int tx = tid & 15, ty = tid >> 4;
    float acc[4][4];
#pragma unroll
    for (int i = 0; i < 4; i++)
#pragma unroll
        for (int j = 0; j < 4; j++) acc[i][j] = 0.f;
#pragma unroll 4
    for (int d = 0; d < 64; d++) {
        float a[4], b[4];
#pragma unroll
        for (int i = 0; i < 4; i++) a[i] = Qs[ty * 4 + i][d];
#pragma unroll
        for (int j = 0; j < 4; j++) b[j] = Ws[d][tx * 4 + j];
#pragma unroll
        for (int i = 0; i < 4; i++)
#pragma unroll
            for (int j = 0; j < 4; j++) acc[i][j] += a[i] * b[j];
    }
#pragma unroll
    for (int i = 0; i < 4; i++) {
        int tok = t0 + ty * 4 + i;
        int b = tok >> 11;
        int qq = tok & 2047;
        size_t base = (((size_t)(b * NHh + h)) * Ss + qq) * HDd + tx * 4;
        uint32_t h0, l0, h1, l1;
        split2(acc[i][0], acc[i][1], h0, l0);
        split2(acc[i][2], acc[i][3], h1, l1);
        uint2 hv = make_uint2(h0, h1), lv = make_uint2(l0, l1);
        *(uint2*)(qwhi + base) = hv;
        *(uint2*)(qwlo + base) = lv;
    }
}

// ================= HMMA flash attention + unification logits =================
// CTA: 128 q-rows for one (b,h). 8 warps x 16 rows. KV tiles of 64 keys, double buffered.
// smem: Qhi|Qlo|QWhi|QWlo (4x16KB) then 2 x (Khi|Klo|KThi|KTlo|Vhi|Vlo (6x8KB) + mask 256B)
#define ATT_KVBUF 49408
#define ATT_SMEM (65536 + 2*ATT_KVBUF)

__device__ __forceinline__ void att_load_kv(uint32_t dst, int b, int h, int k0, int tid,
    const __nv_bfloat16* khi, const __nv_bfloat16* klo,
    const __nv_bfloat16* kthi, const __nv_bfloat16* ktlo,
    const __nv_bfloat16* vhi, const __nv_bfloat16* vlo, const int* mask)
{
#pragma unroll
    for (int i = tid; i < 512; i += 256) {
        int r = i >> 3, c = i & 7;
        uint32_t sw = (uint32_t)(r * 128) + (uint32_t)((c ^ (r & 7)) << 4);
        size_t gk = ((size_t)(b * Ss + k0 + r)) * 2048 + h * 128 + (c << 4);
        size_t gt = ((size_t)(b * Ss + k0 + r)) * 128 + (c << 4);
        CP_ASYNC16(dst + sw,          (const char*)khi + gk);
        CP_ASYNC16(dst + 8192 + sw,   (const char*)klo + gk);
        CP_ASYNC16(dst + 16384 + sw,  (const char*)kthi + gt);
        CP_ASYNC16(dst + 24576 + sw,  (const char*)ktlo + gt);
        CP_ASYNC16(dst + 32768 + sw,  (const char*)vhi + gk);
        CP_ASYNC16(dst + 40960 + sw,  (const char*)vlo + gk);
    }
    if (tid < 16)
        CP_ASYNC16(dst + 49152 + tid * 16, (const char*)mask + ((size_t)(b * Ss + k0)) * 4 + tid * 16);
}

__global__ __launch_bounds__(256, 1)
void attn_hmma(const __nv_bfloat16* __restrict__ qhi, const __nv_bfloat16* __restrict__ qlo,
               const __nv_bfloat16* __restrict__ khi, const __nv_bfloat16* __restrict__ klo,
               const __nv_bfloat16* __restrict__ vhi, const __nv_bfloat16* __restrict__ vlo,
               const __nv_bfloat16* __restrict__ kthi, const __nv_bfloat16* __restrict__ ktlo,
               const __nv_bfloat16* __restrict__ qwhi, const __nv_bfloat16* __restrict__ qwlo,
               const int* __restrict__ mask, float* __restrict__ unif,
               __nv_bfloat16* __restrict__ ohi, __nv_bfloat16* __restrict__ olo)
{
    extern __shared__ char sm_[];
    uint32_t sb = smem_u32(sm_);
    int tid = threadIdx.x, wid = tid >> 5, lid = tid & 31;
    int b = blockIdx.z, h = blockIdx.y, q0 = blockIdx.x * 128;
    const float NEGINF = __int_as_float(0xff800000);

    // ---- Q/QW tiles into smem ----
#pragma unroll
    for (int i = tid; i < 1024; i += 256) {
        int r = i >> 3, c = i & 7;
        uint32_t sw = (uint32_t)(r * 128) + (uint32_t)((c ^ (r & 7)) << 4);
        size_t gq = ((size_t)(b * Ss + q0 + r)) * 2048 + h * 128 + (c << 4);
        size_t gw = (((size_t)(b * NHh + h)) * Ss + q0 + r) * 128 + (c << 4);
        CP_ASYNC16(sb + sw,          (const char*)qhi + gq);
        CP_ASYNC16(sb + 16384 + sw,  (const char*)qlo + gq);
        CP_ASYNC16(sb + 32768 + sw,  (const char*)qwhi + gw);
        CP_ASYNC16(sb + 49152 + sw,  (const char*)qwlo + gw);
    }
    att_load_kv(sb + 65536, b, h, 0, tid, khi, klo, kthi, ktlo, vhi, vlo, mask);
    CP_COMMIT();

    int sub = lid & 7;
    int gA1 = (lid >> 3) & 1, ca = (lid >> 4) & 1;
    int gB2 = (lid >> 4) & 1, cb = (lid >> 3) & 1;
    int arow = wid * 16 + gA1 * 8 + sub;
    uint32_t aoffQ[4];
#pragma unroll
    for (int j = 0; j < 4; j++)
        aoffQ[j] = (uint32_t)(arow * 128) + (uint32_t)(((2 * j + ca) ^ sub) << 4);

    uint32_t qfh[4][4], qfl[4][4];
    float out[32], sv[32], su[32];
    float m0 = -1e30f, m1 = -1e30f, lsum0 = 0.f, lsum1 = 0.f;
#pragma unroll
    for (int i = 0; i < 32; i++) out[i] = 0.f;

    int row0 = q0 + wid * 16 + (lid >> 2);
    int mcol = 2 * (lid & 3);

    for (int kt = 0; kt < 32; kt++) {
        if (kt + 1 < 32) {
            att_load_kv(sb + 65536 + ((kt + 1) & 1) * ATT_KVBUF, b, h, (kt + 1) * 64, tid,
                        khi, klo, kthi, ktlo, vhi, vlo, mask);
            CP_COMMIT();
            CP_WAIT1();
        } else {
            CP_WAIT0();
        }
        __syncthreads();

        if (kt == 0) {
#pragma unroll
            for (int j = 0; j < 4; j++) {
                LDSM_X4(qfh[j][0], qfh[j][1], qfh[j][2], qfh[j][3], sb + aoffQ[j]);
                LDSM_X4(qfl[j][0], qfl[j][1], qfl[j][2], qfl[j][3], sb + 16384 + aoffQ[j]);
            }
        }

        uint32_t cbuf = sb + 65536 + (kt & 1) * ATT_KVBUF;
        int k0 = kt * 64;
#pragma unroll
        for (int i = 0; i < 32; i++) { sv[i] = 0.f; su[i] = 0.f; }

        // ---- val scores: Q . K^T ----
#pragma unroll
        for (int j = 0; j < 4; j++) {
            uint32_t bh[16], bl[16];
#pragma unroll
            for (int p = 0; p < 4; p++) {
                uint32_t bo = (uint32_t)((p * 16 + gB2 * 8 + sub) * 128)
                            + (uint32_t)(((2 * j + cb) ^ sub) << 4);
                LDSM_X4(bh[4*p], bh[4*p+1], bh[4*p+2], bh[4*p+3], cbuf + bo);
                LDSM_X4(bl[4*p], bl[4*p+1], bl[4*p+2], bl[4*p+3], cbuf + 8192 + bo);
            }
#pragma unroll
            for (int jn = 0; jn < 8; jn++) {
                int bi = (jn >> 1) * 4 + (jn & 1) * 2;
                MMA16816(sv + 4*jn, qfh[j], bh[bi], bh[bi+1]);
                MMA16816(sv + 4*jn, qfh[j], bl[bi], bl[bi+1]);
                MMA16816(sv + 4*jn, qfl[j], bh[bi], bh[bi+1]);
            }
        }
        // ---- unif scores: QW . KT^T ----
#pragma unroll
        for (int j = 0; j < 4; j++) {
            uint32_t awh[4], awl[4], bh[16], bl[16];
            LDSM_X4(awh[0], awh[1], awh[2], awh[3], sb + 32768 + aoffQ[j]);
            LDSM_X4(awl[0], awl[1], awl[2], awl[3], sb + 49152 + aoffQ[j]);
#pragma unroll
            for (int p = 0; p < 4; p++) {
                uint32_t bo = (uint32_t)((p * 16 + gB2 * 8 + sub) * 128)
                            + (uint32_t)(((2 * j + cb) ^ sub) << 4);
                LDSM_X4(bh[4*p], bh[4*p+1], bh[4*p+2], bh[4*p+3], cbuf + 16384 + bo);
                LDSM_X4(bl[4*p], bl[4*p+1], bl[4*p+2], bl[4*p+3], cbuf + 24576 + bo);
            }
#pragma unroll
            for (int jn = 0; jn < 8; jn++) {
                int bi = (jn >> 1) * 4 + (jn & 1) * 2;
                MMA16816(su + 4*jn, awh, bh[bi], bh[bi+1]);
                MMA16816(su + 4*jn, awh, bl[bi], bl[bi+1]);
                MMA16816(su + 4*jn, awl, bh[bi], bh[bi+1]);
            }
        }

        // ---- elementwise: unif store, mask, online max ----
        const char* mbuf = sm_ + 65536 + (kt & 1) * ATT_KVBUF + 49152;
        float mn0 = m0, mn1 = m1;
#pragma unroll
        for (int jn = 0; jn < 8; jn++) {
            int colL = jn * 8 + mcol;
            float u0 = su[4*jn]   * SCALE, u1 = su[4*jn+1] * SCALE;
            float u2 = su[4*jn+2] * SCALE, u3 = su[4*jn+3] * SCALE;
            size_t ub = (((size_t)(b * NHh + h)) * Ss + row0) * Ss + k0 + colL;
            *(float2*)(unif + ub)          = make_float2(u0, u1);
            *(float2*)(unif + ub + 8 * Ss) = make_float2(u2, u3);
            su[4*jn] = u0; su[4*jn+1] = u1; su[4*jn+2] = u2; su[4*jn+3] = u3;
            int2 mk = *(const int2*)(mbuf + colL * 4);
            float s0 = mk.x ? sv[4*jn]   * SCALE : NEGINF;
            float s1 = mk.y ? sv[4*jn+1] * SCALE : NEGINF;
            float s2 = mk.x ? sv[4*jn+2] * SCALE : NEGINF;
            float s3 = mk.y ? sv[4*jn+3] * SCALE : NEGINF;
            sv[4*jn] = s0; sv[4*jn+1] = s1; sv[4*jn+2] = s2; sv[4*jn+3] = s3;
            mn0 = fmaxf(mn0, fmaxf(s0, s1));
            mn1 = fmaxf(mn1, fmaxf(s2, s3));
        }
        mn0 = fmaxf(mn0, __shfl_xor_sync(0xffffffffu, mn0, 1));
        mn0 = fmaxf(mn0, __shfl_xor_sync(0xffffffffu, mn0, 2));
        mn1 = fmaxf(mn1, __shfl_xor_sync(0xffffffffu, mn1, 1));
        mn1 = fmaxf(mn1, __shfl_xor_sync(0xffffffffu, mn1, 2));
        float c0 = __expf(m0 - mn0), c1 = __expf(m1 - mn1);
        m0 = mn0; m1 = mn1;
        lsum0 *= c0; lsum1 *= c1;
#pragma unroll
        for (int dn = 0; dn < 8; dn++) {
            out[4*dn]   *= c0; out[4*dn+1] *= c0;
            out[4*dn+2] *= c1; out[4*dn+3] *= c1;
        }

        // ---- p = exp(val-m) * (sigmoid(u)+1e-6), split to bf16 A-frags ----
        uint32_t pah[4][4], pal[4][4];
#pragma unroll
        for (int jn = 0; jn < 8; jn++) {
            float g0 = __fdividef(1.f, 1.f + __expf(-su[4*jn]))   + 1e-6f;
            float g1 = __fdividef(1.f, 1.f + __expf(-su[4*jn+1])) + 1e-6f;
            float g2 = __fdividef(1.f, 1.f + __expf(-su[4*jn+2])) + 1e-6f;
            float g3 = __fdividef(1.f, 1.f + __expf(-su[4*jn+3])) + 1e-6f;
            float p0 = __expf(sv[4*jn]   - mn0) * g0;
            float p1 = __expf(sv[4*jn+1] - mn0) * g1;
            float p2 = __expf(sv[4*jn+2] - mn1) * g2;
            float p3 = __expf(sv[4*jn+3] - mn1) * g3;
            lsum0 += p0 + p1;
            lsum1 += p2 + p3;
            int t = jn >> 1, o = (jn & 1) * 2;
            split2(p0, p1, pah[t][o],     pal[t][o]);
            split2(p2, p3, pah[t][o + 1], pal[t][o + 1]);
        }

        // ---- PV: out += P . V ----
#pragma unroll
        for (int t = 0; t < 4; t++) {
#pragma unroll
            for (int g = 0; g < 4; g++) {
                uint32_t vro = (uint32_t)((t * 16 + (lid & 15)) * 128)
                             + (uint32_t)(((2 * g + ((lid >> 4) & 1)) ^ (lid & 7)) << 4);
                uint32_t vh[4], vl[4];
                LDSM_X4_T(vh[0], vh[1], vh[2], vh[3], cbuf + 32768 + vro);
                LDSM_X4_T(vl[0], vl[1], vl[2], vl[3], cbuf + 40960 + vro);
                MMA16816(out + 4*(2*g),   pah[t], vh[0], vh[1]);
                MMA16816(out + 4*(2*g),   pah[t], vl[0], vl[1]);
                MMA16816(out + 4*(2*g),   pal[t], vh[0], vh[1]);
                MMA16816(out + 4*(2*g+1), pah[t], vh[2], vh[3]);
                MMA16816(out + 4*(2*g+1), pah[t], vl[2], vl[3]);
                MMA16816(out + 4*(2*g+1), pal[t], vh[2], vh[3]);
            }
        }
        __syncthreads();
    }

    // ---- epilogue: normalize, split to bf16, write ----
    lsum0 += __shfl_xor_sync(0xffffffffu, lsum0, 1);
    lsum0 += __shfl_xor_sync(0xffffffffu, lsum0, 2);
    lsum1 += __shfl_xor_sync(0xffffffffu, lsum1, 1);
    lsum1 += __shfl_xor_sync(0xffffffffu, lsum1, 2);
    float i0 = 1.f / lsum0, i1 = 1.f / lsum1;
    size_t r0g = (size_t)(b * Ss + row0);
#pragma unroll
    for (int dn = 0; dn < 8; dn++) {
        int col = h * 64 + dn * 8 + mcol;
        uint32_t h0, l0, h1, l1;
        split2(out[4*dn] * i0,   out[4*dn+1] * i0, h0, l0);
        split2(out[4*dn+2] * i1, out[4*dn+3] * i1, h1, l1);
        *(uint32_t*)(ohi + r0g * Hh + col)       = h0;
        *(uint32_t*)(olo + r0g * Hh + col)       = l0;
        *(uint32_t*)(ohi + (r0g + 8) * Hh + col) = h1;
        *(uint32_t*)(olo + (r0g + 8) * Hh + col) = l1;
    }
}

// ---------------- launch ----------------
extern "C" void kernel_launch(void* const* d_in, const int* in_sizes, int n_in,
                              void* d_out, int out_size)
{
    (void)in_sizes; (void)n_in; (void)out_size;
    const float* x    = (const float*)d_in[0];
    const int*   mask = (const int*)  d_in[1];
    const float* Wq   = (const float*)d_in[2];
    const float* bq   = (const float*)d_in[3];
    const float* Wk   = (const float*)d_in[4];
    const float* bk   = (const float*)d_in[5];
    const float* Wv   = (const float*)d_in[6];
    const float* bv   = (const float*)d_in[7];
    const float* Wo   = (const float*)d_in[8];
    const float* bo   = (const float*)d_in[9];
    const float* Wti  = (const float*)d_in[10];
    const float* bti  = (const float*)d_in[11];
    const float* temb = (const float*)d_in[12];
    const float* Wqt  = (const float*)d_in[13];
    const float* bqt  = (const float*)d_in[14];
    const float* Wkt  = (const float*)d_in[15];
    const float* bkt  = (const float*)d_in[16];
    const float* Wbil = (const float*)d_in[17];

    float* out      = (float*)d_out;
    float* out_y    = out;
    float* out_tl   = out + (size_t)TOKS * Hh;
    float* out_unif = out_tl + (size_t)TOKS * NTt;

    float* qt;
    __nv_bfloat16 *xhi, *xlo, *whi, *wlo, *qh, *ql, *kh, *kl, *vh, *vl, *kth, *ktl, *qwh, *qwl;
    cudaGetSymbolAddress((void**)&qt,   g_qt);
    cudaGetSymbolAddress((void**)&xhi,  g_xhi);
    cudaGetSymbolAddress((void**)&xlo,  g_xlo);
    cudaGetSymbolAddress((void**)&whi,  g_whi);
    cudaGetSymbolAddress((void**)&wlo,  g_wlo);
    cudaGetSymbolAddress((void**)&qh,   g_qhi);
    cudaGetSymbolAddress((void**)&ql,   g_qlo);
    cudaGetSymbolAddress((void**)&kh,   g_khi);
    cudaGetSymbolAddress((void**)&kl,   g_klo);
    cudaGetSymbolAddress((void**)&vh,   g_vhi);
    cudaGetSymbolAddress((void**)&vl,   g_vlo);
    cudaGetSymbolAddress((void**)&kth,  g_kthi);
    cudaGetSymbolAddress((void**)&ktl,  g_ktlo);
    cudaGetSymbolAddress((void**)&qwh,  g_qwhi);
    cudaGetSymbolAddress((void**)&qwl,  g_qwlo);

    const size_t WSZ = (size_t)Hh * Hh;
    cvt_split<<<(TOKS * Hh / 4 + 255) / 256, 256>>>((const float4*)x,
        (__nv_bfloat162*)xhi, (__nv_bfloat162*)xlo, TOKS * Hh / 4);
    cvt_split<<<(WSZ / 4 + 255) / 256, 256>>>((const float4*)Wq,
        (__nv_bfloat162*)(whi + 0 * WSZ), (__nv_bfloat162*)(wlo + 0 * WSZ), WSZ / 4);
    cvt_split<<<(WSZ / 4 + 255) / 256, 256>>>((const float4*)Wk,
        (__nv_bfloat162*)(whi + 1 * WSZ), (__nv_bfloat162*)(wlo + 1 * WSZ), WSZ / 4);
    cvt_split<<<(WSZ / 4 + 255) / 256, 256>>>((const float4*)Wv,
        (__nv_bfloat162*)(whi + 2 * WSZ), (__nv_bfloat162*)(wlo + 2 * WSZ), WSZ / 4);
    cvt_split<<<(WSZ / 4 + 255) / 256, 256>>>((const float4*)Wo,
        (__nv_bfloat162*)(whi + 3 * WSZ), (__nv_bfloat162*)(wlo + 3 * WSZ), WSZ / 4);

    cudaFuncSetAttribute(gemm_hmma, cudaFuncAttributeMaxDynamicSharedMemorySize, GEMM_SMEM);
    dim3 gg(GN / 128, TOKS / 128);
    gemm_hmma<<<gg, 256, GEMM_SMEM>>>(xhi, xlo, whi + 0 * WSZ, wlo + 0 * WSZ, bq, nullptr, qh, ql);
    gemm_hmma<<<gg, 256, GEMM_SMEM>>>(xhi, xlo, whi + 1 * WSZ, wlo + 1 * WSZ, bk, nullptr, kh, kl);
    gemm_hmma<<<gg, 256, GEMM_SMEM>>>(xhi, xlo, whi + 2 * WSZ, wlo + 2 * WSZ, bv, nullptr, vh, vl);

    type_kernel2<<<TOKS / 16, 512>>>(x, Wti, bti, temb, Wqt, bqt, Wkt, bkt, out_tl, qt, kth, ktl);

    qtw_kernel<<<dim3(TOKS / 64, NHh), 256>>>(qt, Wbil, qwh, qwl);

    cudaFuncSetAttribute(attn_hmma, cudaFuncAttributeMaxDynamicSharedMemorySize, ATT_SMEM);
    attn_hmma<<<dim3(Ss / 128, NHh, Bb), 256, ATT_SMEM>>>(qh, ql, kh, kl, vh, vl,
        kth, ktl, qwh, qwl, mask, out_unif, xhi, xlo);

    gemm_hmma<<<gg, 256, GEMM_SMEM>>>(xhi, xlo, whi + 3 * WSZ, wlo + 3 * WSZ, bo, out_y,
                                      nullptr, nullptr);
}

// round 5
// speedup vs baseline: 3.0889x; 1.0302x over previous
#include <cuda_runtime.h>
#include <cuda_bf16.h>
#include <cstdint>
#include <cstddef>

#define Bb 2
#define Ss 2048
#define Hh 1024
#define NHh 16
#define HDd 64
#define NTt 5
#define TOKS (Bb*Ss)          /* 4096 */
#define SCALE 0.125f          /* 1/sqrt(64) */

// ---------------- scratch (static device globals; no allocation) ----------------
__device__ float g_qt[(size_t)TOKS*HDd];
__device__ __nv_bfloat16 g_xhi[(size_t)TOKS*Hh];
__device__ __nv_bfloat16 g_xlo[(size_t)TOKS*Hh];
__device__ __nv_bfloat16 g_whi[(size_t)4*Hh*Hh];
__device__ __nv_bfloat16 g_wlo[(size_t)4*Hh*Hh];
__device__ __nv_bfloat16 g_qhi[(size_t)TOKS*Hh];
__device__ __nv_bfloat16 g_qlo[(size_t)TOKS*Hh];
__device__ __nv_bfloat16 g_khi[(size_t)TOKS*Hh];
__device__ __nv_bfloat16 g_klo[(size_t)TOKS*Hh];
__device__ __nv_bfloat16 g_vhi[(size_t)TOKS*Hh];
__device__ __nv_bfloat16 g_vlo[(size_t)TOKS*Hh];
__device__ __nv_bfloat16 g_kthi[(size_t)TOKS*HDd];
__device__ __nv_bfloat16 g_ktlo[(size_t)TOKS*HDd];
__device__ __nv_bfloat16 g_qwhi[(size_t)Bb*NHh*Ss*HDd];
__device__ __nv_bfloat16 g_qwlo[(size_t)Bb*NHh*Ss*HDd];

// ================= low-level helpers (all plain sm_80+ features) =================
__device__ __forceinline__ uint32_t smem_u32(const void* p) {
    uint32_t a;
    asm("{ .reg .u64 t; cvta.to.shared.u64 t, %1; cvt.u32.u64 %0, t; }" : "=r"(a) : "l"(p));
    return a;
}
#define CP_ASYNC16(saddr, gaddr) \
    asm volatile("cp.async.cg.shared.global [%0], [%1], 16;" :: "r"(saddr), "l"(gaddr))
#define CP_COMMIT() asm volatile("cp.async.commit_group;" ::: "memory")
#define CP_WAIT1()  asm volatile("cp.async.wait_group 1;" ::: "memory")
#define CP_WAIT0()  asm volatile("cp.async.wait_group 0;" ::: "memory")
#define LDSM_X4(r0, r1, r2, r3, addr) \
    asm volatile("ldmatrix.sync.aligned.m8n8.x4.shared.b16 {%0,%1,%2,%3}, [%4];" \
        : "=r"(r0), "=r"(r1), "=r"(r2), "=r"(r3) : "r"(addr))
#define LDSM_X4_T(r0, r1, r2, r3, addr) \
    asm volatile("ldmatrix.sync.aligned.m8n8.x4.trans.shared.b16 {%0,%1,%2,%3}, [%4];" \
        : "=r"(r0), "=r"(r1), "=r"(r2), "=r"(r3) : "r"(addr))
#define MMA16816(c, a, b0, b1) \
    asm volatile("mma.sync.aligned.m16n8k16.row.col.f32.bf16.bf16.f32 " \
        "{%0,%1,%2,%3}, {%4,%5,%6,%7}, {%8,%9}, {%0,%1,%2,%3};" \
        : "+f"((c)[0]), "+f"((c)[1]), "+f"((c)[2]), "+f"((c)[3]) \
        : "r"((a)[0]), "r"((a)[1]), "r"((a)[2]), "r"((a)[3]), "r"(b0), "r"(b1))

__device__ __forceinline__ void split2(float x, float y, uint32_t& hi, uint32_t& lo) {
    __nv_bfloat16 hx = __float2bfloat16(x), hy = __float2bfloat16(y);
    __nv_bfloat16 lx = __float2bfloat16(x - __bfloat162float(hx));
    __nv_bfloat16 ly = __float2bfloat16(y - __bfloat162float(hy));
    __nv_bfloat162 h2(hx, hy), l2(lx, ly);
    hi = *(uint32_t*)&h2; lo = *(uint32_t*)&l2;
}

// ================= fp32 -> bf16 (hi, lo) split =================
__global__ __launch_bounds__(256)
void cvt_split(const float4* __restrict__ in, __nv_bfloat162* __restrict__ hi,
               __nv_bfloat162* __restrict__ lo, int n4)
{
    int i = blockIdx.x * 256 + threadIdx.x;
    if (i >= n4) return;
    float4 f = in[i];
    uint32_t h0, l0, h1, l1;
    split2(f.x, f.y, h0, l0);
    split2(f.z, f.w, h1, l1);
    ((uint32_t*)hi)[2*i]   = h0; ((uint32_t*)hi)[2*i+1] = h1;
    ((uint32_t*)lo)[2*i]   = l0; ((uint32_t*)lo)[2*i+1] = l1;
}

// 4 weight matrices in one launch (grid.y selects)
__global__ __launch_bounds__(256)
void cvt_split_w4(const float4* __restrict__ W0, const float4* __restrict__ W1,
                  const float4* __restrict__ W2, const float4* __restrict__ W3,
                  __nv_bfloat16* __restrict__ hi, __nv_bfloat16* __restrict__ lo)
{
    const int n4 = Hh * Hh / 4;
    int i = blockIdx.x * 256 + threadIdx.x;
    if (i >= n4) return;
    int z = blockIdx.y;
    const float4* in = (z == 0) ? W0 : (z == 1) ? W1 : (z == 2) ? W2 : W3;
    float4 f = in[i];
    uint32_t h0, l0, h1, l1;
    split2(f.x, f.y, h0, l0);
    split2(f.z, f.w, h1, l1);
    size_t base = (size_t)z * Hh * Hh + (size_t)i * 4;
    *(uint32_t*)(hi + base)     = h0; *(uint32_t*)(hi + base + 2) = h1;
    *(uint32_t*)(lo + base)     = l0; *(uint32_t*)(lo + base + 2) = l1;
}

// ================= HMMA bf16-split GEMM core =================
#define GN 1024
#define BUF_BYTES 65536
#define OFF_AL 16384
#define OFF_WH 32768
#define OFF_WL 49152
#define GEMM_SMEM (2*BUF_BYTES + 512)

__device__ __forceinline__ void load_chunk_mma(
    uint32_t sbuf, int kc_bytes, int bm, int bn, int tid,
    const __nv_bfloat16* Ahi, const __nv_bfloat16* Alo,
    const __nv_bfloat16* Whi, const __nv_bfloat16* Wlo)
{
#pragma unroll
    for (int i = tid; i < 1024; i += 256) {
        int r = i >> 3, c = i & 7;
        uint32_t sw = (uint32_t)(r * 128) + (uint32_t)((c ^ (r & 7)) << 4);
        size_t goA = ((size_t)(bm + r) << 11) + kc_bytes + (c << 4);
        size_t goW = ((size_t)(bn + r) << 11) + kc_bytes + (c << 4);
        CP_ASYNC16(sbuf + sw,          (const char*)Ahi + goA);
        CP_ASYNC16(sbuf + OFF_AL + sw, (const char*)Alo + goA);
        CP_ASYNC16(sbuf + OFF_WH + sw, (const char*)Whi + goW);
        CP_ASYNC16(sbuf + OFF_WL + sw, (const char*)Wlo + goW);
    }
}

__device__ __forceinline__ void gemm_body(
    const __nv_bfloat16* Ahi, const __nv_bfloat16* Alo,
    const __nv_bfloat16* Whi, const __nv_bfloat16* Wlo,
    const float* bias, float* Cf, __nv_bfloat16* Chi, __nv_bfloat16* Clo,
    char* sm_, int bm, int bn)
{
    uint32_t sb = smem_u32(sm_);
    float* bias_s = (float*)(sm_ + 2 * BUF_BYTES);
    int tid = threadIdx.x, wid = tid >> 5, lid = tid & 31;

    if (tid < 128) bias_s[tid] = bias[bn + tid];

    int warp_row = (wid & 1) * 64;
    int warp_col = (wid >> 1) * 32;
    int sub = lid & 7;
    int gA1 = (lid >> 3) & 1;
    int ca  = (lid >> 4) & 1;
    int gB2 = (lid >> 4) & 1;
    int cb  = (lid >> 3) & 1;
    int swz = sub;

    uint32_t aBase[4], bBase[2];
#pragma unroll
    for (int i = 0; i < 4; i++)
        aBase[i] = (uint32_t)((warp_row + i * 16 + gA1 * 8 + sub) * 128);
#pragma unroll
    for (int p = 0; p < 2; p++)
        bBase[p] = (uint32_t)((warp_col + p * 16 + gB2 * 8 + sub) * 128);

    float acc[4][4][4];
#pragma unroll
    for (int i = 0; i < 4; i++)
#pragma unroll
        for (int jn = 0; jn < 4; jn++)
#pragma unroll
            for (int r = 0; r < 4; r++) acc[i][jn][r] = 0.f;

    load_chunk_mma(sb, 0, bm, bn, tid, Ahi, Alo, Whi, Wlo);
    CP_COMMIT();

    for (int c = 0; c < 16; c++) {
        if (c + 1 < 16) {
            load_chunk_mma(sb + ((c + 1) & 1) * BUF_BYTES, (c + 1) * 128, bm, bn, tid,
                           Ahi, Alo, Whi, Wlo);
            CP_COMMIT();
            CP_WAIT1();
        } else {
            CP_WAIT0();
        }
        __syncthreads();

        uint32_t bufoff = sb + (c & 1) * BUF_BYTES;
#pragma unroll
        for (int j = 0; j < 4; j++) {
            uint32_t ah[4][4], al[4][4], bh[2][4], bl[2][4];
#pragma unroll
            for (int i = 0; i < 4; i++) {
                uint32_t ad = bufoff + aBase[i] + (uint32_t)((((2 * j + ca) ^ swz)) << 4);
                LDSM_X4(ah[i][0], ah[i][1], ah[i][2], ah[i][3], ad);
                LDSM_X4(al[i][0], al[i][1], al[i][2], al[i][3], ad + OFF_AL);
            }
#pragma unroll
            for (int p = 0; p < 2; p++) {
                uint32_t bd = bufoff + bBase[p] + (uint32_t)((((2 * j + cb) ^ swz)) << 4);
                LDSM_X4(bh[p][0], bh[p][1], bh[p][2], bh[p][3], bd + OFF_WH);
                LDSM_X4(bl[p][0], bl[p][1], bl[p][2], bl[p][3], bd + OFF_WL);
            }
#pragma unroll
            for (int i = 0; i < 4; i++) {
#pragma unroll
                for (int jn = 0; jn < 4; jn++) {
                    int p = jn >> 1, q = (jn & 1) * 2;
                    MMA16816(acc[i][jn], ah[i], bh[p][q], bh[p][q + 1]);
                    MMA16816(acc[i][jn], ah[i], bl[p][q], bl[p][q + 1]);
                    MMA16816(acc[i][jn], al[i], bh[p][q], bh[p][q + 1]);
                }
            }
        }
        __syncthreads();
    }

    int lr = lid >> 2, lc = (lid & 3) * 2;
#pragma unroll
    for (int i = 0; i < 4; i++) {
#pragma unroll
        for (int jn = 0; jn < 4; jn++) {
            int row = bm + warp_row + i * 16 + lr;
            int colL = warp_col + jn * 8 + lc;
            int col = bn + colL;
            float b0 = bias_s[colL], b1 = bias_s[colL + 1];
            float v00 = acc[i][jn][0] + b0, v01 = acc[i][jn][1] + b1;
            float v10 = acc[i][jn][2] + b0, v11 = acc[i][jn][3] + b1;
            if (Cf) {
                *(float2*)(Cf + (size_t)row * GN + col)       = make_float2(v00, v01);
                *(float2*)(Cf + (size_t)(row + 8) * GN + col) = make_float2(v10, v11);
            }
            if (Chi) {
                uint32_t h0, l0, h1, l1;
                split2(v00, v01, h0, l0);
                split2(v10, v11, h1, l1);
                *(uint32_t*)(Chi + (size_t)row * GN + col)       = h0;
                *(uint32_t*)(Clo + (size_t)row * GN + col)       = l0;
                *(uint32_t*)(Chi + (size_t)(row + 8) * GN + col) = h1;
                *(uint32_t*)(Clo + (size_t)(row + 8) * GN + col) = l1;
            }
        }
    }
}

// fused Q/K/V projection: grid.z selects which projection
__global__ __launch_bounds__(256)
void gemm_qkv(const __nv_bfloat16* __restrict__ xhi, const __nv_bfloat16* __restrict__ xlo,
              const __nv_bfloat16* __restrict__ whi, const __nv_bfloat16* __restrict__ wlo,
              const float* __restrict__ bq, const float* __restrict__ bk,
              const float* __restrict__ bv,
              __nv_bfloat16* __restrict__ qh, __nv_bfloat16* __restrict__ ql,
              __nv_bfloat16* __restrict__ kh, __nv_bfloat16* __restrict__ kl,
              __nv_bfloat16* __restrict__ vh, __nv_bfloat16* __restrict__ vl)
{
    extern __shared__ char sm_[];
    int z = blockIdx.z;
    const size_t WSZ = (size_t)Hh * Hh;
    const float* bias = (z == 0) ? bq : (z == 1) ? bk : bv;
    __nv_bfloat16* Chi = (z == 0) ? qh : (z == 1) ? kh : vh;
    __nv_bfloat16* Clo = (z == 0) ? ql : (z == 1) ? kl : vl;
    gemm_body(xhi, xlo, whi + z * WSZ, wlo + z * WSZ, bias, nullptr, Chi, Clo,
              sm_, blockIdx.y * 128, blockIdx.x * 128);
}

// O projection: fp32 output
__global__ __launch_bounds__(256)
void gemm_o(const __nv_bfloat16* __restrict__ ahi, const __nv_bfloat16* __restrict__ alo,
            const __nv_bfloat16* __restrict__ whi, const __nv_bfloat16* __restrict__ wlo,
            const float* __restrict__ bias, float* __restrict__ Cf)
{
    extern __shared__ char sm_[];
    gemm_body(ahi, alo, whi, wlo, bias, Cf, nullptr, nullptr,
              sm_, blockIdx.y * 128, blockIdx.x * 128);
}

// ---------------- type inference: warp-per-token ----------------
__global__ __launch_bounds__(512)
void type_kernel2(const float* __restrict__ x, const float* __restrict__ Wti,
                  const float* __restrict__ bti, const float* __restrict__ temb,
                  const float* __restrict__ Wqt, const float* __restrict__ bqt,
                  const float* __restrict__ Wkt, const float* __restrict__ bkt,
                  float* __restrict__ tl_out, float* __restrict__ qt,
                  __nv_bfloat16* __restrict__ kthi, __nv_bfloat16* __restrict__ ktlo)
{
    __shared__ float sWti[NTt * Hh];
    __shared__ float stemb[NTt * HDd];
    __shared__ float slat[16][HDd];
    int tid = threadIdx.x, wid = tid >> 5, lid = tid & 31;
    for (int i = tid; i < NTt * Hh; i += 512) sWti[i] = Wti[i];
    for (int i = tid; i < NTt * HDd; i += 512) stemb[i] = temb[i];
    __syncthreads();

    int tok = blockIdx.x * 16 + wid;
    const float* xr = x + (size_t)tok * Hh;
    float xv[32];
#pragma unroll
    for (int j = 0; j < 32; j++) xv[j] = xr[lid + 32 * j];

    float lg[NTt];
#pragma unroll
    for (int t = 0; t < NTt; t++) {
        float s = 0.f;
#pragma unroll
        for (int j = 0; j < 32; j++) s += xv[j] * sWti[t * Hh + lid + 32 * j];
        s += __shfl_xor_sync(0xffffffffu, s, 16);
        s += __shfl_xor_sync(0xffffffffu, s, 8);
        s += __shfl_xor_sync(0xffffffffu, s, 4);
        s += __shfl_xor_sync(0xffffffffu, s, 2);
        s += __shfl_xor_sync(0xffffffffu, s, 1);
        lg[t] = s + bti[t];
    }
    if (lid == 0) {
        float* tl = tl_out + (size_t)tok * NTt;
#pragma unroll
        for (int t = 0; t < NTt; t++) tl[t] = lg[t];
    }
    float mx = lg[0];
#pragma unroll
    for (int t = 1; t < NTt; t++) mx = fmaxf(mx, lg[t]);
    float e[NTt], se = 0.f;
#pragma unroll
    for (int t = 0; t < NTt; t++) { e[t] = expf(lg[t] - mx); se += e[t]; }
    float inv = 1.f / se;

    float la0 = 0.f, la1 = 0.f;
#pragma unroll
    for (int t = 0; t < NTt; t++) {
        float p = e[t] * inv;
        la0 += p * stemb[t * HDd + lid];
        la1 += p * stemb[t * HDd + lid + 32];
    }
    slat[wid][lid] = la0;
    slat[wid][lid + 32] = la1;
    __syncwarp();

#pragma unroll
    for (int rep = 0; rep < 2; rep++) {
        int d = lid + rep * 32;
        float a = bqt[d], c = bkt[d];
        const float* wq = Wqt + (size_t)d * HDd;
        const float* wk = Wkt + (size_t)d * HDd;
#pragma unroll
        for (int e2 = 0; e2 < HDd; e2++) {
            float lv = slat[wid][e2];
            a += lv * wq[e2];
            c += lv * wk[e2];
        }
        qt[(size_t)tok * HDd + d] = a;
        __nv_bfloat16 hc = __float2bfloat16(c);
        kthi[(size_t)tok * HDd + d] = hc;
        ktlo[(size_t)tok * HDd + d] = __float2bfloat16(c - __bfloat162float(hc));
    }
}

// ---------------- qtW[b,h,q,e] = sum_d qt[b,q,d] * W_bil[h,d,e] (bf16 split out) ----------------
__global__ __launch_bounds__(256)
void qtw_kernel(const float* __restrict__ qt, const float* __restrict__ Wb,
                __nv_bfloat16* __restrict__ qwhi, __nv_bfloat16* __restrict__ qwlo)
{
    __shared__ float Qs[64][65];
    __shared__ float Ws[64][65];
    int h = blockIdx.y;
    int t0 = blockIdx.x * 64;
    int tid = threadIdx.x;
    for (int i = tid; i < 4096; i += 256) {
        int r = i >> 6, c = i & 63;
        Qs[r][c] = qt[(size_t)(t0 + r) * HDd + c];
        Ws[r][c] = Wb[(size_t)h * 4096 + i];
    }
    __syncthreads();
    int tx = tid & 15, ty = tid >> 4;
    float acc[4][4];
#pragma unroll
    for (int i = 0; i < 4; i++)
#pragma unroll
        for (int j = 0; j < 4; j++) acc[i][j] = 0.f;
#pragma unroll 4
    for (int d = 0; d < 64; d++) {
        float a[4], b[4];
#pragma unroll
        for (int i = 0; i < 4; i++) a[i] = Qs[ty * 4 + i][d];
#pragma unroll
        for (int j = 0; j < 4; j++) b[j] = Ws[d][tx * 4 + j];
#pragma unroll
        for (int i = 0; i < 4; i++)
#pragma unroll
            for (int j = 0; j < 4; j++) acc[i][j] += a[i] * b[j];
    }
#pragma unroll
    for (int i = 0; i < 4; i++) {
        int tok = t0 + ty * 4 + i;
        int b = tok >> 11;
        int qq = tok & 2047;
        size_t base = (((size_t)(b * NHh + h)) * Ss + qq) * HDd + tx * 4;
        uint32_t h0, l0, h1, l1;
        split2(acc[i][0], acc[i][1], h0, l0);
        split2(acc[i][2], acc[i][3], h1, l1);
        uint2 hv = make_uint2(h0, h1), lv = make_uint2(l0, l1);
        *(uint2*)(qwhi + base) = hv;
        *(uint2*)(qwlo + base) = lv;
    }
}

// ================= HMMA flash attention v2: 128 threads, 64 q-rows, 32-key tiles =================
// smem: Qhi|Qlo|QWhi|QWlo (4x8KB = 32KB) then 2 x (Khi|Klo|KThi|KTlo|Vhi|Vlo (6x4KB) + mask 128B)
#define AKV 24704
#define ATT_SMEM (32768 + 2*AKV)
#define NKT (Ss/32)       /* 64 kv tiles */

__device__ __forceinline__ void att_load_kv(uint32_t dst, int b, int h, int k0, int tid,
    const __nv_bfloat16* khi, const __nv_bfloat16* klo,
    const __nv_bfloat16* kthi, const __nv_bfloat16* ktlo,
    const __nv_bfloat16* vhi, const __nv_bfloat16* vlo, const int* mask)
{
#pragma unroll
    for (int i = tid; i < 256; i += 128) {
        int r = i >> 3, c = i & 7;
        uint32_t sw = (uint32_t)(r * 128) + (uint32_t)((c ^ (r & 7)) << 4);
        size_t gk = ((size_t)(b * Ss + k0 + r)) * 2048 + h * 128 + (c << 4);
        size_t gt = ((size_t)(b * Ss + k0 + r)) * 128 + (c << 4);
        CP_ASYNC16(dst + sw,          (const char*)khi + gk);
        CP_ASYNC16(dst + 4096 + sw,   (const char*)klo + gk);
        CP_ASYNC16(dst + 8192 + sw,   (const char*)kthi + gt);
        CP_ASYNC16(dst + 12288 + sw,  (const char*)ktlo + gt);
        CP_ASYNC16(dst + 16384 + sw,  (const char*)vhi + gk);
        CP_ASYNC16(dst + 20480 + sw,  (const char*)vlo + gk);
    }
    if (tid < 8)
        CP_ASYNC16(dst + 24576 + tid * 16, (const char*)mask + ((size_t)(b * Ss + k0)) * 4 + tid * 16);
}

__global__ __launch_bounds__(128, 2)
void attn_hmma(const __nv_bfloat16* __restrict__ qhi, const __nv_bfloat16* __restrict__ qlo,
               const __nv_bfloat16* __restrict__ khi, const __nv_bfloat16* __restrict__ klo,
               const __nv_bfloat16* __restrict__ vhi, const __nv_bfloat16* __restrict__ vlo,
               const __nv_bfloat16* __restrict__ kthi, const __nv_bfloat16* __restrict__ ktlo,
               const __nv_bfloat16* __restrict__ qwhi, const __nv_bfloat16* __restrict__ qwlo,
               const int* __restrict__ mask, float* __restrict__ unif,
               __nv_bfloat16* __restrict__ ohi, __nv_bfloat16* __restrict__ olo)
{
    extern __shared__ char sm_[];
    uint32_t sb = smem_u32(sm_);
    int tid = threadIdx.x, wid = tid >> 5, lid = tid & 31;
    int b = blockIdx.z, h = blockIdx.y, q0 = blockIdx.x * 64;
    const float NEGINF = __int_as_float(0xff800000);

    // ---- Q/QW tiles into smem (64 rows x 128B each of 4 arrays) ----
#pragma unroll
    for (int i = tid; i < 512; i += 128) {
        int r = i >> 3, c = i & 7;
        uint32_t sw = (uint32_t)(r * 128) + (uint32_t)((c ^ (r & 7)) << 4);
        size_t gq = ((size_t)(b * Ss + q0 + r)) * 2048 + h * 128 + (c << 4);
        size_t gw = (((size_t)(b * NHh + h)) * Ss + q0 + r) * 128 + (c << 4);
        CP_ASYNC16(sb + sw,          (const char*)qhi + gq);
        CP_ASYNC16(sb + 8192 + sw,   (const char*)qlo + gq);
        CP_ASYNC16(sb + 16384 + sw,  (const char*)qwhi + gw);
        CP_ASYNC16(sb + 24576 + sw,  (const char*)qwlo + gw);
    }
    att_load_kv(sb + 32768, b, h, 0, tid, khi, klo, kthi, ktlo, vhi, vlo, mask);
    CP_COMMIT();

    int sub = lid & 7;
    int gA1 = (lid >> 3) & 1, ca = (lid >> 4) & 1;
    int gB2 = (lid >> 4) & 1, cb = (lid >> 3) & 1;
    int arow = wid * 16 + gA1 * 8 + sub;
    uint32_t aoffQ[4];
#pragma unroll
    for (int j = 0; j < 4; j++)
        aoffQ[j] = (uint32_t)(arow * 128) + (uint32_t)(((2 * j + ca) ^ sub) << 4);

    uint32_t qfh[4][4], qfl[4][4];
    float out[32], sv[16], su[16];
    float m0 = -1e30f, m1 = -1e30f, lsum0 = 0.f, lsum1 = 0.f;
#pragma unroll
    for (int i = 0; i < 32; i++) out[i] = 0.f;

    int row0 = q0 + wid * 16 + (lid >> 2);
    int mcol = 2 * (lid & 3);

    for (int kt = 0; kt < NKT; kt++) {
        if (kt + 1 < NKT) {
            att_load_kv(sb + 32768 + ((kt + 1) & 1) * AKV, b, h, (kt + 1) * 32, tid,
                        khi, klo, kthi, ktlo, vhi, vlo, mask);
            CP_COMMIT();
            CP_WAIT1();
        } else {
            CP_WAIT0();
        }
        __syncthreads();

        if (kt == 0) {
#pragma unroll
            for (int j = 0; j < 4; j++) {
                LDSM_X4(qfh[j][0], qfh[j][1], qfh[j][2], qfh[j][3], sb + aoffQ[j]);
                LDSM_X4(qfl[j][0], qfl[j][1], qfl[j][2], qfl[j][3], sb + 8192 + aoffQ[j]);
            }
        }

        uint32_t cbuf = sb + 32768 + (kt & 1) * AKV;
        int k0 = kt * 32;
#pragma unroll
        for (int i = 0; i < 16; i++) { sv[i] = 0.f; su[i] = 0.f; }

        // ---- val scores: Q . K^T ----
#pragma unroll
        for (int j = 0; j < 4; j++) {
            uint32_t bh[8], bl[8];
#pragma unroll
            for (int p = 0; p < 2; p++) {
                uint32_t bo = (uint32_t)((p * 16 + gB2 * 8 + sub) * 128)
                            + (uint32_t)(((2 * j + cb) ^ sub) << 4);
                LDSM_X4(bh[4*p], bh[4*p+1], bh[4*p+2], bh[4*p+3], cbuf + bo);
                LDSM_X4(bl[4*p], bl[4*p+1], bl[4*p+2], bl[4*p+3], cbuf + 4096 + bo);
            }
#pragma unroll
            for (int jn = 0; jn < 4; jn++) {
                int bi = (jn >> 1) * 4 + (jn & 1) * 2;
                MMA16816(sv + 4*jn, qfh[j], bh[bi], bh[bi+1]);
                MMA16816(sv + 4*jn, qfh[j], bl[bi], bl[bi+1]);
                MMA16816(sv + 4*jn, qfl[j], bh[bi], bh[bi+1]);
            }
        }
        // ---- unif scores: QW . KT^T ----
#pragma unroll
        for (int j = 0; j < 4; j++) {
            uint32_t awh[4], awl[4], bh[8], bl[8];
            LDSM_X4(awh[0], awh[1], awh[2], awh[3], sb + 16384 + aoffQ[j]);
            LDSM_X4(awl[0], awl[1], awl[2], awl[3], sb + 24576 + aoffQ[j]);
#pragma unroll
            for (int p = 0; p < 2; p++) {
                uint32_t bo = (uint32_t)((p * 16 + gB2 * 8 + sub) * 128)
                            + (uint32_t)(((2 * j + cb) ^ sub) << 4);
                LDSM_X4(bh[4*p], bh[4*p+1], bh[4*p+2], bh[4*p+3], cbuf + 8192 + bo);
                LDSM_X4(bl[4*p], bl[4*p+1], bl[4*p+2], bl[4*p+3], cbuf + 12288 + bo);
            }
#pragma unroll
            for (int jn = 0; jn < 4; jn++) {
                int bi = (jn >> 1) * 4 + (jn & 1) * 2;
                MMA16816(su + 4*jn, awh, bh[bi], bh[bi+1]);
                MMA16816(su + 4*jn, awh, bl[bi], bl[bi+1]);
                MMA16816(su + 4*jn, awl, bh[bi], bh[bi+1]);
            }
        }

        // ---- elementwise: unif store, mask, online max ----
        const char* mbuf = sm_ + 32768 + (kt & 1) * AKV + 24576;
        float mn0 = m0, mn1 = m1;
#pragma unroll
        for (int jn = 0; jn < 4; jn++) {
            int colL = jn * 8 + mcol;
            float u0 = su[4*jn]   * SCALE, u1 = su[4*jn+1] * SCALE;
            float u2 = su[4*jn+2] * SCALE, u3 = su[4*jn+3] * SCALE;
            size_t ub = (((size_t)(b * NHh + h)) * Ss + row0) * Ss + k0 + colL;
            *(float2*)(unif + ub)          = make_float2(u0, u1);
            *(float2*)(unif + ub + 8 * Ss) = make_float2(u2, u3);
            su[4*jn] = u0; su[4*jn+1] = u1; su[4*jn+2] = u2; su[4*jn+3] = u3;
            int2 mk = *(const int2*)(mbuf + colL * 4);
            float s0 = mk.x ? sv[4*jn]   * SCALE : NEGINF;
            float s1 = mk.y ? sv[4*jn+1] * SCALE : NEGINF;
            float s2 = mk.x ? sv[4*jn+2] * SCALE : NEGINF;
            float s3 = mk.y ? sv[4*jn+3] * SCALE : NEGINF;
            sv[4*jn] = s0; sv[4*jn+1] = s1; sv[4*jn+2] = s2; sv[4*jn+3] = s3;
            mn0 = fmaxf(mn0, fmaxf(s0, s1));
            mn1 = fmaxf(mn1, fmaxf(s2, s3));
        }
        mn0 = fmaxf(mn0, __shfl_xor_sync(0xffffffffu, mn0, 1));
        mn0 = fmaxf(mn0, __shfl_xor_sync(0xffffffffu, mn0, 2));
        mn1 = fmaxf(mn1, __shfl_xor_sync(0xffffffffu, mn1, 1));
        mn1 = fmaxf(mn1, __shfl_xor_sync(0xffffffffu, mn1, 2));
        float c0 = __expf(m0 - mn0), c1 = __expf(m1 - mn1);
        m0 = mn0; m1 = mn1;
        lsum0 *= c0; lsum1 *= c1;
#pragma unroll
        for (int dn = 0; dn < 8; dn++) {
            out[4*dn]   *= c0; out[4*dn+1] *= c0;
            out[4*dn+2] *= c1; out[4*dn+3] *= c1;
        }

        // ---- p = exp(val-m) * (sigmoid(u)+1e-6), split to bf16 A-frags ----
        uint32_t pah[2][4], pal[2][4];
#pragma unroll
        for (int jn = 0; jn < 4; jn++) {
            float g0 = __fdividef(1.f, 1.f + __expf(-su[4*jn]))   + 1e-6f;
            float g1 = __fdividef(1.f, 1.f + __expf(-su[4*jn+1])) + 1e-6f;
            float g2 = __fdividef(1.f, 1.f + __expf(-su[4*jn+2])) + 1e-6f;
            float g3 = __fdividef(1.f, 1.f + __expf(-su[4*jn+3])) + 1e-6f;
            float p0 = __expf(sv[4*jn]   - mn0) * g0;
            float p1 = __expf(sv[4*jn+1] - mn0) * g1;
            float p2 = __expf(sv[4*jn+2] - mn1) * g2;
            float p3 = __expf(sv[4*jn+3] - mn1) * g3;
            lsum0 += p0 + p1;
            lsum1 += p2 + p3;
            int t = jn >> 1, o = (jn & 1) * 2;
            split2(p0, p1, pah[t][o],     pal[t][o]);
            split2(p2, p3, pah[t][o + 1], pal[t][o + 1]);
        }

        // ---- PV: out += P . V ----
#pragma unroll
        for (int t = 0; t < 2; t++) {
#pragma unroll
            for (int g = 0; g < 4; g++) {
                uint32_t vro = (uint32_t)((t * 16 + (lid & 15)) * 128)
                             + (uint32_t)(((2 * g + ((lid >> 4) & 1)) ^ (lid & 7)) << 4);
                uint32_t vh[4], vl[4];
                LDSM_X4_T(vh[0], vh[1], vh[2], vh[3], cbuf + 16384 + vro);
                LDSM_X4_T(vl[0], vl[1], vl[2], vl[3], cbuf + 20480 + vro);
                MMA16816(out + 4*(2*g),   pah[t], vh[0], vh[1]);
                MMA16816(out + 4*(2*g),   pah[t], vl[0], vl[1]);
                MMA16816(out + 4*(2*g),   pal[t], vh[0], vh[1]);
                MMA16816(out + 4*(2*g+1), pah[t], vh[2], vh[3]);
                MMA16816(out + 4*(2*g+1), pah[t], vl[2], vl[3]);
                MMA16816(out + 4*(2*g+1), pal[t], vh[2], vh[3]);
            }
        }
        __syncthreads();
    }

    // ---- epilogue: normalize, split to bf16, write ----
    lsum0 += __shfl_xor_sync(0xffffffffu, lsum0, 1);
    lsum0 += __shfl_xor_sync(0xffffffffu, lsum0, 2);
    lsum1 += __shfl_xor_sync(0xffffffffu, lsum1, 1);
    lsum1 += __shfl_xor_sync(0xffffffffu, lsum1, 2);
    float i0 = 1.f / lsum0, i1 = 1.f / lsum1;
    size_t r0g = (size_t)(b * Ss + row0);
#pragma unroll
    for (int dn = 0; dn < 8; dn++) {
        int col = h * 64 + dn * 8 + mcol;
        uint32_t h0, l0, h1, l1;
        split2(out[4*dn] * i0,   out[4*dn+1] * i0, h0, l0);
        split2(out[4*dn+2] * i1, out[4*dn+3] * i1, h1, l1);
        *(uint32_t*)(ohi + r0g * Hh + col)       = h0;
        *(uint32_t*)(olo + r0g * Hh + col)       = l0;
        *(uint32_t*)(ohi + (r0g + 8) * Hh + col) = h1;
        *(uint32_t*)(olo + (r0g + 8) * Hh + col) = l1;
    }
}

// ---------------- launch ----------------
extern "C" void kernel_launch(void* const* d_in, const int* in_sizes, int n_in,
                              void* d_out, int out_size)
{
    (void)in_sizes; (void)n_in; (void)out_size;
    const float* x    = (const float*)d_in[0];
    const int*   mask = (const int*)  d_in[1];
    const float* Wq   = (const float*)d_in[2];
    const float* bq   = (const float*)d_in[3];
    const float* Wk   = (const float*)d_in[4];
    const float* bk   = (const float*)d_in[5];
    const float* Wv   = (const float*)d_in[6];
    const float* bv   = (const float*)d_in[7];
    const float* Wo   = (const float*)d_in[8];
    const float* bo   = (const float*)d_in[9];
    const float* Wti  = (const float*)d_in[10];
    const float* bti  = (const float*)d_in[11];
    const float* temb = (const float*)d_in[12];
    const float* Wqt  = (const float*)d_in[13];
    const float* bqt  = (const float*)d_in[14];
    const float* Wkt  = (const float*)d_in[15];
    const float* bkt  = (const float*)d_in[16];
    const float* Wbil = (const float*)d_in[17];

    float* out      = (float*)d_out;
    float* out_y    = out;
    float* out_tl   = out + (size_t)TOKS * Hh;
    float* out_unif = out_tl + (size_t)TOKS * NTt;

    float* qt;
    __nv_bfloat16 *xhi, *xlo, *whi, *wlo, *qh, *ql, *kh, *kl, *vh, *vl, *kth, *ktl, *qwh, *qwl;
    cudaGetSymbolAddress((void**)&qt,   g_qt);
    cudaGetSymbolAddress((void**)&xhi,  g_xhi);
    cudaGetSymbolAddress((void**)&xlo,  g_xlo);
    cudaGetSymbolAddress((void**)&whi,  g_whi);
    cudaGetSymbolAddress((void**)&wlo,  g_wlo);
    cudaGetSymbolAddress((void**)&qh,   g_qhi);
    cudaGetSymbolAddress((void**)&ql,   g_qlo);
    cudaGetSymbolAddress((void**)&kh,   g_khi);
    cudaGetSymbolAddress((void**)&kl,   g_klo);
    cudaGetSymbolAddress((void**)&vh,   g_vhi);
    cudaGetSymbolAddress((void**)&vl,   g_vlo);
    cudaGetSymbolAddress((void**)&kth,  g_kthi);
    cudaGetSymbolAddress((void**)&ktl,  g_ktlo);
    cudaGetSymbolAddress((void**)&qwh,  g_qwhi);
    cudaGetSymbolAddress((void**)&qwl,  g_qwlo);

    const size_t WSZ = (size_t)Hh * Hh;
    cvt_split<<<(TOKS * Hh / 4 + 255) / 256, 256>>>((const float4*)x,
        (__nv_bfloat162*)xhi, (__nv_bfloat162*)xlo, TOKS * Hh / 4);
    cvt_split_w4<<<dim3((WSZ / 4 + 255) / 256, 4), 256>>>(
        (const float4*)Wq, (const float4*)Wk, (const float4*)Wv, (const float4*)Wo,
        whi, wlo);

    cudaFuncSetAttribute(gemm_qkv, cudaFuncAttributeMaxDynamicSharedMemorySize, GEMM_SMEM);
    cudaFuncSetAttribute(gemm_o,   cudaFuncAttributeMaxDynamicSharedMemorySize, GEMM_SMEM);
    gemm_qkv<<<dim3(GN / 128, TOKS / 128, 3), 256, GEMM_SMEM>>>(
        xhi, xlo, whi, wlo, bq, bk, bv, qh, ql, kh, kl, vh, vl);

    type_kernel2<<<TOKS / 16, 512>>>(x, Wti, bti, temb, Wqt, bqt, Wkt, bkt, out_tl, qt, kth, ktl);

    qtw_kernel<<<dim3(TOKS / 64, NHh), 256>>>(qt, Wbil, qwh, qwl);

    cudaFuncSetAttribute(attn_hmma, cudaFuncAttributeMaxDynamicSharedMemorySize, ATT_SMEM);
    attn_hmma<<<dim3(Ss / 64, NHh, Bb), 128, ATT_SMEM>>>(qh, ql, kh, kl, vh, vl,
        kth, ktl, qwh, qwl, mask, out_unif, xhi, xlo);

    gemm_o<<<dim3(GN / 128, TOKS / 128), 256, GEMM_SMEM>>>(xhi, xlo,
        whi + 3 * WSZ, wlo + 3 * WSZ, bo, out_y);
}

// round 6
// speedup vs baseline: 3.7356x; 1.2093x over previous
#include <cuda_runtime.h>
#include <cuda_bf16.h>
#include <cstdint>
#include <cstddef>

#define Bb 2
#define Ss 2048
#define Hh 1024
#define NHh 16
#define HDd 64
#define NTt 5
#define TOKS (Bb*Ss)          /* 4096 */
#define SCALE 0.125f          /* 1/sqrt(64) */

// ---------------- scratch (static device globals; no allocation) ----------------
__device__ float g_qt[(size_t)TOKS*HDd];
__device__ __nv_bfloat16 g_xhi[(size_t)TOKS*Hh];
__device__ __nv_bfloat16 g_xlo[(size_t)TOKS*Hh];
__device__ __nv_bfloat16 g_whi[(size_t)4*Hh*Hh];
__device__ __nv_bfloat16 g_wlo[(size_t)4*Hh*Hh];
__device__ __nv_bfloat16 g_qhi[(size_t)TOKS*Hh];
__device__ __nv_bfloat16 g_qlo[(size_t)TOKS*Hh];
__device__ __nv_bfloat16 g_khi[(size_t)TOKS*Hh];
__device__ __nv_bfloat16 g_klo[(size_t)TOKS*Hh];
__device__ __nv_bfloat16 g_vhi[(size_t)TOKS*Hh];
__device__ __nv_bfloat16 g_vlo[(size_t)TOKS*Hh];
__device__ __nv_bfloat16 g_kthi[(size_t)TOKS*HDd];
__device__ __nv_bfloat16 g_ktlo[(size_t)TOKS*HDd];
__device__ __nv_bfloat16 g_qwhi[(size_t)Bb*NHh*Ss*HDd];
__device__ __nv_bfloat16 g_qwlo[(size_t)Bb*NHh*Ss*HDd];

// ================= low-level helpers (all plain sm_80+ features) =================
__device__ __forceinline__ uint32_t smem_u32(const void* p) {
    uint32_t a;
    asm("{ .reg .u64 t; cvta.to.shared.u64 t, %1; cvt.u32.u64 %0, t; }" : "=r"(a) : "l"(p));
    return a;
}
#define CP_ASYNC16(saddr, gaddr) \
    asm volatile("cp.async.cg.shared.global [%0], [%1], 16;" :: "r"(saddr), "l"(gaddr))
#define CP_COMMIT() asm volatile("cp.async.commit_group;" ::: "memory")
#define CP_WAIT1()  asm volatile("cp.async.wait_group 1;" ::: "memory")
#define CP_WAIT0()  asm volatile("cp.async.wait_group 0;" ::: "memory")
#define LDSM_X4(r0, r1, r2, r3, addr) \
    asm volatile("ldmatrix.sync.aligned.m8n8.x4.shared.b16 {%0,%1,%2,%3}, [%4];" \
        : "=r"(r0), "=r"(r1), "=r"(r2), "=r"(r3) : "r"(addr))
#define LDSM_X4_T(r0, r1, r2, r3, addr) \
    asm volatile("ldmatrix.sync.aligned.m8n8.x4.trans.shared.b16 {%0,%1,%2,%3}, [%4];" \
        : "=r"(r0), "=r"(r1), "=r"(r2), "=r"(r3) : "r"(addr))
#define MMA16816(c, a, b0, b1) \
    asm volatile("mma.sync.aligned.m16n8k16.row.col.f32.bf16.bf16.f32 " \
        "{%0,%1,%2,%3}, {%4,%5,%6,%7}, {%8,%9}, {%0,%1,%2,%3};" \
        : "+f"((c)[0]), "+f"((c)[1]), "+f"((c)[2]), "+f"((c)[3]) \
        : "r"((a)[0]), "r"((a)[1]), "r"((a)[2]), "r"((a)[3]), "r"(b0), "r"(b1))

__device__ __forceinline__ void split2(float x, float y, uint32_t& hi, uint32_t& lo) {
    __nv_bfloat16 hx = __float2bfloat16(x), hy = __float2bfloat16(y);
    __nv_bfloat16 lx = __float2bfloat16(x - __bfloat162float(hx));
    __nv_bfloat16 ly = __float2bfloat16(y - __bfloat162float(hy));
    __nv_bfloat162 h2(hx, hy), l2(lx, ly);
    hi = *(uint32_t*)&h2; lo = *(uint32_t*)&l2;
}

// ================= fp32 -> bf16 (hi, lo) split =================
__global__ __launch_bounds__(256)
void cvt_split(const float4* __restrict__ in, __nv_bfloat162* __restrict__ hi,
               __nv_bfloat162* __restrict__ lo, int n4)
{
    int i = blockIdx.x * 256 + threadIdx.x;
    if (i >= n4) return;
    float4 f = in[i];
    uint32_t h0, l0, h1, l1;
    split2(f.x, f.y, h0, l0);
    split2(f.z, f.w, h1, l1);
    ((uint32_t*)hi)[2*i]   = h0; ((uint32_t*)hi)[2*i+1] = h1;
    ((uint32_t*)lo)[2*i]   = l0; ((uint32_t*)lo)[2*i+1] = l1;
}

// 4 weight matrices in one launch (grid.y selects)
__global__ __launch_bounds__(256)
void cvt_split_w4(const float4* __restrict__ W0, const float4* __restrict__ W1,
                  const float4* __restrict__ W2, const float4* __restrict__ W3,
                  __nv_bfloat16* __restrict__ hi, __nv_bfloat16* __restrict__ lo)
{
    const int n4 = Hh * Hh / 4;
    int i = blockIdx.x * 256 + threadIdx.x;
    if (i >= n4) return;
    int z = blockIdx.y;
    const float4* in = (z == 0) ? W0 : (z == 1) ? W1 : (z == 2) ? W2 : W3;
    float4 f = in[i];
    uint32_t h0, l0, h1, l1;
    split2(f.x, f.y, h0, l0);
    split2(f.z, f.w, h1, l1);
    size_t base = (size_t)z * Hh * Hh + (size_t)i * 4;
    *(uint32_t*)(hi + base)     = h0; *(uint32_t*)(hi + base + 2) = h1;
    *(uint32_t*)(lo + base)     = l0; *(uint32_t*)(lo + base + 2) = l1;
}

// ================= HMMA bf16-split GEMM core =================
#define GN 1024
#define BUF_BYTES 65536
#define OFF_AL 16384
#define OFF_WH 32768
#define OFF_WL 49152
#define GEMM_SMEM (2*BUF_BYTES + 512)

__device__ __forceinline__ void load_chunk_mma(
    uint32_t sbuf, int kc_bytes, int bm, int bn, int tid,
    const __nv_bfloat16* Ahi, const __nv_bfloat16* Alo,
    const __nv_bfloat16* Whi, const __nv_bfloat16* Wlo)
{
#pragma unroll
    for (int i = tid; i < 1024; i += 256) {
        int r = i >> 3, c = i & 7;
        uint32_t sw = (uint32_t)(r * 128) + (uint32_t)((c ^ (r & 7)) << 4);
        size_t goA = ((size_t)(bm + r) << 11) + kc_bytes + (c << 4);
        size_t goW = ((size_t)(bn + r) << 11) + kc_bytes + (c << 4);
        CP_ASYNC16(sbuf + sw,          (const char*)Ahi + goA);
        CP_ASYNC16(sbuf + OFF_AL + sw, (const char*)Alo + goA);
        CP_ASYNC16(sbuf + OFF_WH + sw, (const char*)Whi + goW);
        CP_ASYNC16(sbuf + OFF_WL + sw, (const char*)Wlo + goW);
    }
}

__device__ __forceinline__ void gemm_body(
    const __nv_bfloat16* Ahi, const __nv_bfloat16* Alo,
    const __nv_bfloat16* Whi, const __nv_bfloat16* Wlo,
    const float* bias, float* Cf, __nv_bfloat16* Chi, __nv_bfloat16* Clo,
    char* sm_, int bm, int bn)
{
    uint32_t sb = smem_u32(sm_);
    float* bias_s = (float*)(sm_ + 2 * BUF_BYTES);
    int tid = threadIdx.x, wid = tid >> 5, lid = tid & 31;

    if (tid < 128) bias_s[tid] = bias[bn + tid];

    int warp_row = (wid & 1) * 64;
    int warp_col = (wid >> 1) * 32;
    int sub = lid & 7;
    int gA1 = (lid >> 3) & 1;
    int ca  = (lid >> 4) & 1;
    int gB2 = (lid >> 4) & 1;
    int cb  = (lid >> 3) & 1;
    int swz = sub;

    uint32_t aBase[4], bBase[2];
#pragma unroll
    for (int i = 0; i < 4; i++)
        aBase[i] = (uint32_t)((warp_row + i * 16 + gA1 * 8 + sub) * 128);
#pragma unroll
    for (int p = 0; p < 2; p++)
        bBase[p] = (uint32_t)((warp_col + p * 16 + gB2 * 8 + sub) * 128);

    float acc[4][4][4];
#pragma unroll
    for (int i = 0; i < 4; i++)
#pragma unroll
        for (int jn = 0; jn < 4; jn++)
#pragma unroll
            for (int r = 0; r < 4; r++) acc[i][jn][r] = 0.f;

    load_chunk_mma(sb, 0, bm, bn, tid, Ahi, Alo, Whi, Wlo);
    CP_COMMIT();

    for (int c = 0; c < 16; c++) {
        if (c + 1 < 16) {
            load_chunk_mma(sb + ((c + 1) & 1) * BUF_BYTES, (c + 1) * 128, bm, bn, tid,
                           Ahi, Alo, Whi, Wlo);
            CP_COMMIT();
            CP_WAIT1();
        } else {
            CP_WAIT0();
        }
        __syncthreads();

        uint32_t bufoff = sb + (c & 1) * BUF_BYTES;
#pragma unroll
        for (int j = 0; j < 4; j++) {
            uint32_t ah[4][4], al[4][4], bh[2][4], bl[2][4];
#pragma unroll
            for (int i = 0; i < 4; i++) {
                uint32_t ad = bufoff + aBase[i] + (uint32_t)((((2 * j + ca) ^ swz)) << 4);
                LDSM_X4(ah[i][0], ah[i][1], ah[i][2], ah[i][3], ad);
                LDSM_X4(al[i][0], al[i][1], al[i][2], al[i][3], ad + OFF_AL);
            }
#pragma unroll
            for (int p = 0; p < 2; p++) {
                uint32_t bd = bufoff + bBase[p] + (uint32_t)((((2 * j + cb) ^ swz)) << 4);
                LDSM_X4(bh[p][0], bh[p][1], bh[p][2], bh[p][3], bd + OFF_WH);
                LDSM_X4(bl[p][0], bl[p][1], bl[p][2], bl[p][3], bd + OFF_WL);
            }
#pragma unroll
            for (int i = 0; i < 4; i++) {
#pragma unroll
                for (int jn = 0; jn < 4; jn++) {
                    int p = jn >> 1, q = (jn & 1) * 2;
                    MMA16816(acc[i][jn], ah[i], bh[p][q], bh[p][q + 1]);
                    MMA16816(acc[i][jn], ah[i], bl[p][q], bl[p][q + 1]);
                    MMA16816(acc[i][jn], al[i], bh[p][q], bh[p][q + 1]);
                }
            }
        }
        __syncthreads();
    }

    int lr = lid >> 2, lc = (lid & 3) * 2;
#pragma unroll
    for (int i = 0; i < 4; i++) {
#pragma unroll
        for (int jn = 0; jn < 4; jn++) {
            int row = bm + warp_row + i * 16 + lr;
            int colL = warp_col + jn * 8 + lc;
            int col = bn + colL;
            float b0 = bias_s[colL], b1 = bias_s[colL + 1];
            float v00 = acc[i][jn][0] + b0, v01 = acc[i][jn][1] + b1;
            float v10 = acc[i][jn][2] + b0, v11 = acc[i][jn][3] + b1;
            if (Cf) {
                *(float2*)(Cf + (size_t)row * GN + col)       = make_float2(v00, v01);
                *(float2*)(Cf + (size_t)(row + 8) * GN + col) = make_float2(v10, v11);
            }
            if (Chi) {
                uint32_t h0, l0, h1, l1;
                split2(v00, v01, h0, l0);
                split2(v10, v11, h1, l1);
                *(uint32_t*)(Chi + (size_t)row * GN + col)       = h0;
                *(uint32_t*)(Clo + (size_t)row * GN + col)       = l0;
                *(uint32_t*)(Chi + (size_t)(row + 8) * GN + col) = h1;
                *(uint32_t*)(Clo + (size_t)(row + 8) * GN + col) = l1;
            }
        }
    }
}

// fused Q/K/V projection: grid.z selects which projection
__global__ __launch_bounds__(256)
void gemm_qkv(const __nv_bfloat16* __restrict__ xhi, const __nv_bfloat16* __restrict__ xlo,
              const __nv_bfloat16* __restrict__ whi, const __nv_bfloat16* __restrict__ wlo,
              const float* __restrict__ bq, const float* __restrict__ bk,
              const float* __restrict__ bv,
              __nv_bfloat16* __restrict__ qh, __nv_bfloat16* __restrict__ ql,
              __nv_bfloat16* __restrict__ kh, __nv_bfloat16* __restrict__ kl,
              __nv_bfloat16* __restrict__ vh, __nv_bfloat16* __restrict__ vl)
{
    extern __shared__ char sm_[];
    int z = blockIdx.z;
    const size_t WSZ = (size_t)Hh * Hh;
    const float* bias = (z == 0) ? bq : (z == 1) ? bk : bv;
    __nv_bfloat16* Chi = (z == 0) ? qh : (z == 1) ? kh : vh;
    __nv_bfloat16* Clo = (z == 0) ? ql : (z == 1) ? kl : vl;
    gemm_body(xhi, xlo, whi + z * WSZ, wlo + z * WSZ, bias, nullptr, Chi, Clo,
              sm_, blockIdx.y * 128, blockIdx.x * 128);
}

// O projection: fp32 output
__global__ __launch_bounds__(256)
void gemm_o(const __nv_bfloat16* __restrict__ ahi, const __nv_bfloat16* __restrict__ alo,
            const __nv_bfloat16* __restrict__ whi, const __nv_bfloat16* __restrict__ wlo,
            const float* __restrict__ bias, float* __restrict__ Cf)
{
    extern __shared__ char sm_[];
    gemm_body(ahi, alo, whi, wlo, bias, Cf, nullptr, nullptr,
              sm_, blockIdx.y * 128, blockIdx.x * 128);
}

// ---------------- type inference v3: warp-per-token, all weights in smem ----------------
#define TK_SMEM ((NTt*Hh + NTt*HDd + 16*HDd + 2*HDd*65) * 4)

__global__ __launch_bounds__(512)
void type_kernel3(const float* __restrict__ x, const float* __restrict__ Wti,
                  const float* __restrict__ bti, const float* __restrict__ temb,
                  const float* __restrict__ Wqt, const float* __restrict__ bqt,
                  const float* __restrict__ Wkt, const float* __restrict__ bkt,
                  float* __restrict__ tl_out, float* __restrict__ qt,
                  __nv_bfloat16* __restrict__ kthi, __nv_bfloat16* __restrict__ ktlo)
{
    extern __shared__ float smf[];
    float* sWti  = smf;                       // NTt*Hh
    float* stemb = sWti + NTt * Hh;           // NTt*HDd
    float* slat  = stemb + NTt * HDd;         // 16*HDd
    float* sWqt  = slat + 16 * HDd;           // HDd*65 (padded)
    float* sWkt  = sWqt + HDd * 65;           // HDd*65

    int tid = threadIdx.x, wid = tid >> 5, lid = tid & 31;
    for (int i = tid; i < NTt * Hh; i += 512) sWti[i] = Wti[i];
    for (int i = tid; i < NTt * HDd; i += 512) stemb[i] = temb[i];
    for (int i = tid; i < HDd * HDd; i += 512) {
        int r = i >> 6, c = i & 63;
        sWqt[r * 65 + c] = Wqt[i];
        sWkt[r * 65 + c] = Wkt[i];
    }
    __syncthreads();

    int tok = blockIdx.x * 16 + wid;
    const float* xr = x + (size_t)tok * Hh;
    float xv[32];
#pragma unroll
    for (int j = 0; j < 32; j++) xv[j] = xr[lid + 32 * j];

    float lg[NTt];
#pragma unroll
    for (int t = 0; t < NTt; t++) {
        float s = 0.f;
#pragma unroll
        for (int j = 0; j < 32; j++) s += xv[j] * sWti[t * Hh + lid + 32 * j];
        s += __shfl_xor_sync(0xffffffffu, s, 16);
        s += __shfl_xor_sync(0xffffffffu, s, 8);
        s += __shfl_xor_sync(0xffffffffu, s, 4);
        s += __shfl_xor_sync(0xffffffffu, s, 2);
        s += __shfl_xor_sync(0xffffffffu, s, 1);
        lg[t] = s + bti[t];
    }
    if (lid == 0) {
        float* tl = tl_out + (size_t)tok * NTt;
#pragma unroll
        for (int t = 0; t < NTt; t++) tl[t] = lg[t];
    }
    float mx = lg[0];
#pragma unroll
    for (int t = 1; t < NTt; t++) mx = fmaxf(mx, lg[t]);
    float e[NTt], se = 0.f;
#pragma unroll
    for (int t = 0; t < NTt; t++) { e[t] = expf(lg[t] - mx); se += e[t]; }
    float inv = 1.f / se;

    float la0 = 0.f, la1 = 0.f;
#pragma unroll
    for (int t = 0; t < NTt; t++) {
        float p = e[t] * inv;
        la0 += p * stemb[t * HDd + lid];
        la1 += p * stemb[t * HDd + lid + 32];
    }
    slat[wid * HDd + lid] = la0;
    slat[wid * HDd + lid + 32] = la1;
    __syncwarp();

#pragma unroll
    for (int rep = 0; rep < 2; rep++) {
        int d = lid + rep * 32;
        float a = bqt[d], c = bkt[d];
        const float* wq = sWqt + d * 65;
        const float* wk = sWkt + d * 65;
        const float* la = slat + wid * HDd;
#pragma unroll
        for (int e2 = 0; e2 < HDd; e2++) {
            float lv = la[e2];
            a += lv * wq[e2];
            c += lv * wk[e2];
        }
        qt[(size_t)tok * HDd + d] = a;
        __nv_bfloat16 hc = __float2bfloat16(c);
        kthi[(size_t)tok * HDd + d] = hc;
        ktlo[(size_t)tok * HDd + d] = __float2bfloat16(c - __bfloat162float(hc));
    }
}

// ---------------- qtW[b,h,q,e] = sum_d qt[b,q,d] * W_bil[h,d,e] (bf16 split out) ----------------
__global__ __launch_bounds__(256)
void qtw_kernel(const float* __restrict__ qt, const float* __restrict__ Wb,
                __nv_bfloat16* __restrict__ qwhi, __nv_bfloat16* __restrict__ qwlo)
{
    __shared__ float Qs[64][65];
    __shared__ float Ws[64][65];
    int h = blockIdx.y;
    int t0 = blockIdx.x * 64;
    int tid = threadIdx.x;
    for (int i = tid; i < 4096; i += 256) {
        int r = i >> 6, c = i & 63;
        Qs[r][c] = qt[(size_t)(t0 + r) * HDd + c];
        Ws[r][c] = Wb[(size_t)h * 4096 + i];
    }
    __syncthreads();
    int tx = tid & 15, ty = tid >> 4;
    float acc[4][4];
#pragma unroll
    for (int i = 0; i < 4; i++)
#pragma unroll
        for (int j = 0; j < 4; j++) acc[i][j] = 0.f;
#pragma unroll 4
    for (int d = 0; d < 64; d++) {
        float a[4], b[4];
#pragma unroll
        for (int i = 0; i < 4; i++) a[i] = Qs[ty * 4 + i][d];
#pragma unroll
        for (int j = 0; j < 4; j++) b[j] = Ws[d][tx * 4 + j];
#pragma unroll
        for (int i = 0; i < 4; i++)
#pragma unroll
            for (int j = 0; j < 4; j++) acc[i][j] += a[i] * b[j];
    }
#pragma unroll
    for (int i = 0; i < 4; i++) {
        int tok = t0 + ty * 4 + i;
        int b = tok >> 11;
        int qq = tok & 2047;
        size_t base = (((size_t)(b * NHh + h)) * Ss + qq) * HDd + tx * 4;
        uint32_t h0, l0, h1, l1;
        split2(acc[i][0], acc[i][1], h0, l0);
        split2(acc[i][2], acc[i][3], h1, l1);
        uint2 hv = make_uint2(h0, h1), lv = make_uint2(l0, l1);
        *(uint2*)(qwhi + base) = hv;
        *(uint2*)(qwlo + base) = lv;
    }
}

// ================= HMMA flash attention v2: 128 threads, 64 q-rows, 32-key tiles =================
#define AKV 24704
#define ATT_SMEM (32768 + 2*AKV)
#define NKT (Ss/32)       /* 64 kv tiles */

__device__ __forceinline__ void att_load_kv(uint32_t dst, int b, int h, int k0, int tid,
    const __nv_bfloat16* khi, const __nv_bfloat16* klo,
    const __nv_bfloat16* kthi, const __nv_bfloat16* ktlo,
    const __nv_bfloat16* vhi, const __nv_bfloat16* vlo, const int* mask)
{
#pragma unroll
    for (int i = tid; i < 256; i += 128) {
        int r = i >> 3, c = i & 7;
        uint32_t sw = (uint32_t)(r * 128) + (uint32_t)((c ^ (r & 7)) << 4);
        size_t gk = ((size_t)(b * Ss + k0 + r)) * 2048 + h * 128 + (c << 4);
        size_t gt = ((size_t)(b * Ss + k0 + r)) * 128 + (c << 4);
        CP_ASYNC16(dst + sw,          (const char*)khi + gk);
        CP_ASYNC16(dst + 4096 + sw,   (const char*)klo + gk);
        CP_ASYNC16(dst + 8192 + sw,   (const char*)kthi + gt);
        CP_ASYNC16(dst + 12288 + sw,  (const char*)ktlo + gt);
        CP_ASYNC16(dst + 16384 + sw,  (const char*)vhi + gk);
        CP_ASYNC16(dst + 20480 + sw,  (const char*)vlo + gk);
    }
    if (tid < 8)
        CP_ASYNC16(dst + 24576 + tid * 16, (const char*)mask + ((size_t)(b * Ss + k0)) * 4 + tid * 16);
}

__global__ __launch_bounds__(128, 2)
void attn_hmma(const __nv_bfloat16* __restrict__ qhi, const __nv_bfloat16* __restrict__ qlo,
               const __nv_bfloat16* __restrict__ khi, const __nv_bfloat16* __restrict__ klo,
               const __nv_bfloat16* __restrict__ vhi, const __nv_bfloat16* __restrict__ vlo,
               const __nv_bfloat16* __restrict__ kthi, const __nv_bfloat16* __restrict__ ktlo,
               const __nv_bfloat16* __restrict__ qwhi, const __nv_bfloat16* __restrict__ qwlo,
               const int* __restrict__ mask, float* __restrict__ unif,
               __nv_bfloat16* __restrict__ ohi, __nv_bfloat16* __restrict__ olo)
{
    extern __shared__ char sm_[];
    uint32_t sb = smem_u32(sm_);
    int tid = threadIdx.x, wid = tid >> 5, lid = tid & 31;
    int b = blockIdx.z, h = blockIdx.y, q0 = blockIdx.x * 64;
    const float NEGINF = __int_as_float(0xff800000);

    // ---- Q/QW tiles into smem (64 rows x 128B each of 4 arrays) ----
#pragma unroll
    for (int i = tid; i < 512; i += 128) {
        int r = i >> 3, c = i & 7;
        uint32_t sw = (uint32_t)(r * 128) + (uint32_t)((c ^ (r & 7)) << 4);
        size_t gq = ((size_t)(b * Ss + q0 + r)) * 2048 + h * 128 + (c << 4);
        size_t gw = (((size_t)(b * NHh + h)) * Ss + q0 + r) * 128 + (c << 4);
        CP_ASYNC16(sb + sw,          (const char*)qhi + gq);
        CP_ASYNC16(sb + 8192 + sw,   (const char*)qlo + gq);
        CP_ASYNC16(sb + 16384 + sw,  (const char*)qwhi + gw);
        CP_ASYNC16(sb + 24576 + sw,  (const char*)qwlo + gw);
    }
    att_load_kv(sb + 32768, b, h, 0, tid, khi, klo, kthi, ktlo, vhi, vlo, mask);
    CP_COMMIT();

    int sub = lid & 7;
    int gA1 = (lid >> 3) & 1, ca = (lid >> 4) & 1;
    int gB2 = (lid >> 4) & 1, cb = (lid >> 3) & 1;
    int arow = wid * 16 + gA1 * 8 + sub;
    uint32_t aoffQ[4];
#pragma unroll
    for (int j = 0; j < 4; j++)
        aoffQ[j] = (uint32_t)(arow * 128) + (uint32_t)(((2 * j + ca) ^ sub) << 4);

    uint32_t qfh[4][4], qfl[4][4], awh[4][4], awl[4][4];
    float out[32], sv[16], su[16];
    float m0 = -1e30f, m1 = -1e30f, lsum0 = 0.f, lsum1 = 0.f;
#pragma unroll
    for (int i = 0; i < 32; i++) out[i] = 0.f;

    int row0 = q0 + wid * 16 + (lid >> 2);
    int mcol = 2 * (lid & 3);

    for (int kt = 0; kt < NKT; kt++) {
        if (kt + 1 < NKT) {
            att_load_kv(sb + 32768 + ((kt + 1) & 1) * AKV, b, h, (kt + 1) * 32, tid,
                        khi, klo, kthi, ktlo, vhi, vlo, mask);
            CP_COMMIT();
            CP_WAIT1();
        } else {
            CP_WAIT0();
        }
        __syncthreads();

        if (kt == 0) {
            // Q and QW A-fragments are loop-invariant: load once
#pragma unroll
            for (int j = 0; j < 4; j++) {
                LDSM_X4(qfh[j][0], qfh[j][1], qfh[j][2], qfh[j][3], sb + aoffQ[j]);
                LDSM_X4(qfl[j][0], qfl[j][1], qfl[j][2], qfl[j][3], sb + 8192 + aoffQ[j]);
                LDSM_X4(awh[j][0], awh[j][1], awh[j][2], awh[j][3], sb + 16384 + aoffQ[j]);
                LDSM_X4(awl[j][0], awl[j][1], awl[j][2], awl[j][3], sb + 24576 + aoffQ[j]);
            }
        }

        uint32_t cbuf = sb + 32768 + (kt & 1) * AKV;
        int k0 = kt * 32;
#pragma unroll
        for (int i = 0; i < 16; i++) { sv[i] = 0.f; su[i] = 0.f; }

        // ---- val scores: Q . K^T ----
#pragma unroll
        for (int j = 0; j < 4; j++) {
            uint32_t bh[8], bl[8];
#pragma unroll
            for (int p = 0; p < 2; p++) {
                uint32_t bo = (uint32_t)((p * 16 + gB2 * 8 + sub) * 128)
                            + (uint32_t)(((2 * j + cb) ^ sub) << 4);
                LDSM_X4(bh[4*p], bh[4*p+1], bh[4*p+2], bh[4*p+3], cbuf + bo);
                LDSM_X4(bl[4*p], bl[4*p+1], bl[4*p+2], bl[4*p+3], cbuf + 4096 + bo);
            }
#pragma unroll
            for (int jn = 0; jn < 4; jn++) {
                int bi = (jn >> 1) * 4 + (jn & 1) * 2;
                MMA16816(sv + 4*jn, qfh[j], bh[bi], bh[bi+1]);
                MMA16816(sv + 4*jn, qfh[j], bl[bi], bl[bi+1]);
                MMA16816(sv + 4*jn, qfl[j], bh[bi], bh[bi+1]);
            }
        }
        // ---- unif scores: QW . KT^T ----
#pragma unroll
        for (int j = 0; j < 4; j++) {
            uint32_t bh[8], bl[8];
#pragma unroll
            for (int p = 0; p < 2; p++) {
                uint32_t bo = (uint32_t)((p * 16 + gB2 * 8 + sub) * 128)
                            + (uint32_t)(((2 * j + cb) ^ sub) << 4);
                LDSM_X4(bh[4*p], bh[4*p+1], bh[4*p+2], bh[4*p+3], cbuf + 8192 + bo);
                LDSM_X4(bl[4*p], bl[4*p+1], bl[4*p+2], bl[4*p+3], cbuf + 12288 + bo);
            }
#pragma unroll
            for (int jn = 0; jn < 4; jn++) {
                int bi = (jn >> 1) * 4 + (jn & 1) * 2;
                MMA16816(su + 4*jn, awh[j], bh[bi], bh[bi+1]);
                MMA16816(su + 4*jn, awh[j], bl[bi], bl[bi+1]);
                MMA16816(su + 4*jn, awl[j], bh[bi], bh[bi+1]);
            }
        }

        // ---- elementwise: unif store, mask, online max ----
        const char* mbuf = sm_ + 32768 + (kt & 1) * AKV + 24576;
        float mn0 = m0, mn1 = m1;
#pragma unroll
        for (int jn = 0; jn < 4; jn++) {
            int colL = jn * 8 + mcol;
            float u0 = su[4*jn]   * SCALE, u1 = su[4*jn+1] * SCALE;
            float u2 = su[4*jn+2] * SCALE, u3 = su[4*jn+3] * SCALE;
            size_t ub = (((size_t)(b * NHh + h)) * Ss + row0) * Ss + k0 + colL;
            *(float2*)(unif + ub)          = make_float2(u0, u1);
            *(float2*)(unif + ub + 8 * Ss) = make_float2(u2, u3);
            su[4*jn] = u0; su[4*jn+1] = u1; su[4*jn+2] = u2; su[4*jn+3] = u3;
            int2 mk = *(const int2*)(mbuf + colL * 4);
            float s0 = mk.x ? sv[4*jn]   * SCALE : NEGINF;
            float s1 = mk.y ? sv[4*jn+1] * SCALE : NEGINF;
            float s2 = mk.x ? sv[4*jn+2] * SCALE : NEGINF;
            float s3 = mk.y ? sv[4*jn+3] * SCALE : NEGINF;
            sv[4*jn] = s0; sv[4*jn+1] = s1; sv[4*jn+2] = s2; sv[4*jn+3] = s3;
            mn0 = fmaxf(mn0, fmaxf(s0, s1));
            mn1 = fmaxf(mn1, fmaxf(s2, s3));
        }
        mn0 = fmaxf(mn0, __shfl_xor_sync(0xffffffffu, mn0, 1));
        mn0 = fmaxf(mn0, __shfl_xor_sync(0xffffffffu, mn0, 2));
        mn1 = fmaxf(mn1, __shfl_xor_sync(0xffffffffu, mn1, 1));
        mn1 = fmaxf(mn1, __shfl_xor_sync(0xffffffffu, mn1, 2));
        float c0 = __expf(m0 - mn0), c1 = __expf(m1 - mn1);
        m0 = mn0; m1 = mn1;
        lsum0 *= c0; lsum1 *= c1;
#pragma unroll
        for (int dn = 0; dn < 8; dn++) {
            out[4*dn]   *= c0; out[4*dn+1] *= c0;
            out[4*dn+2] *= c1; out[4*dn+3] *= c1;
        }

        // ---- p = exp(val-m) * (sigmoid(u)+1e-6), split to bf16 A-frags ----
        uint32_t pah[2][4], pal[2][4];
#pragma unroll
        for (int jn = 0; jn < 4; jn++) {
            float g0 = __fdividef(1.f, 1.f + __expf(-su[4*jn]))   + 1e-6f;
            float g1 = __fdividef(1.f, 1.f + __expf(-su[4*jn+1])) + 1e-6f;
            float g2 = __fdividef(1.f, 1.f + __expf(-su[4*jn+2])) + 1e-6f;
            float g3 = __fdividef(1.f, 1.f + __expf(-su[4*jn+3])) + 1e-6f;
            float p0 = __expf(sv[4*jn]   - mn0) * g0;
            float p1 = __expf(sv[4*jn+1] - mn0) * g1;
            float p2 = __expf(sv[4*jn+2] - mn1) * g2;
            float p3 = __expf(sv[4*jn+3] - mn1) * g3;
            lsum0 += p0 + p1;
            lsum1 += p2 + p3;
            int t = jn >> 1, o = (jn & 1) * 2;
            split2(p0, p1, pah[t][o],     pal[t][o]);
            split2(p2, p3, pah[t][o + 1], pal[t][o + 1]);
        }

        // ---- PV: out += P . V ----
#pragma unroll
        for (int t = 0; t < 2; t++) {
#pragma unroll
            for (int g = 0; g < 4; g++) {
                uint32_t vro = (uint32_t)((t * 16 + (lid & 15)) * 128)
                             + (uint32_t)(((2 * g + ((lid >> 4) & 1)) ^ (lid & 7)) << 4);
                uint32_t vh[4], vl[4];
                LDSM_X4_T(vh[0], vh[1], vh[2], vh[3], cbuf + 16384 + vro);
                LDSM_X4_T(vl[0], vl[1], vl[2], vl[3], cbuf + 20480 + vro);
                MMA16816(out + 4*(2*g),   pah[t], vh[0], vh[1]);
                MMA16816(out + 4*(2*g),   pah[t], vl[0], vl[1]);
                MMA16816(out + 4*(2*g),   pal[t], vh[0], vh[1]);
                MMA16816(out + 4*(2*g+1), pah[t], vh[2], vh[3]);
                MMA16816(out + 4*(2*g+1), pah[t], vl[2], vl[3]);
                MMA16816(out + 4*(2*g+1), pal[t], vh[2], vh[3]);
            }
        }
        __syncthreads();
    }

    // ---- epilogue: normalize, split to bf16, write ----
    lsum0 += __shfl_xor_sync(0xffffffffu, lsum0, 1);
    lsum0 += __shfl_xor_sync(0xffffffffu, lsum0, 2);
    lsum1 += __shfl_xor_sync(0xffffffffu, lsum1, 1);
    lsum1 += __shfl_xor_sync(0xffffffffu, lsum1, 2);
    float i0 = 1.f / lsum0, i1 = 1.f / lsum1;
    size_t r0g = (size_t)(b * Ss + row0);
#pragma unroll
    for (int dn = 0; dn < 8; dn++) {
        int col = h * 64 + dn * 8 + mcol;
        uint32_t h0, l0, h1, l1;
        split2(out[4*dn] * i0,   out[4*dn+1] * i0, h0, l0);
        split2(out[4*dn+2] * i1, out[4*dn+3] * i1, h1, l1);
        *(uint32_t*)(ohi + r0g * Hh + col)       = h0;
        *(uint32_t*)(olo + r0g * Hh + col)       = l0;
        *(uint32_t*)(ohi + (r0g + 8) * Hh + col) = h1;
        *(uint32_t*)(olo + (r0g + 8) * Hh + col) = l1;
    }
}

// ---------------- launch ----------------
extern "C" void kernel_launch(void* const* d_in, const int* in_sizes, int n_in,
                              void* d_out, int out_size)
{
    (void)in_sizes; (void)n_in; (void)out_size;
    const float* x    = (const float*)d_in[0];
    const int*   mask = (const int*)  d_in[1];
    const float* Wq   = (const float*)d_in[2];
    const float* bq   = (const float*)d_in[3];
    const float* Wk   = (const float*)d_in[4];
    const float* bk   = (const float*)d_in[5];
    const float* Wv   = (const float*)d_in[6];
    const float* bv   = (const float*)d_in[7];
    const float* Wo   = (const float*)d_in[8];
    const float* bo   = (const float*)d_in[9];
    const float* Wti  = (const float*)d_in[10];
    const float* bti  = (const float*)d_in[11];
    const float* temb = (const float*)d_in[12];
    const float* Wqt  = (const float*)d_in[13];
    const float* bqt  = (const float*)d_in[14];
    const float* Wkt  = (const float*)d_in[15];
    const float* bkt  = (const float*)d_in[16];
    const float* Wbil = (const float*)d_in[17];

    float* out      = (float*)d_out;
    float* out_y    = out;
    float* out_tl   = out + (size_t)TOKS * Hh;
    float* out_unif = out_tl + (size_t)TOKS * NTt;

    float* qt;
    __nv_bfloat16 *xhi, *xlo, *whi, *wlo, *qh, *ql, *kh, *kl, *vh, *vl, *kth, *ktl, *qwh, *qwl;
    cudaGetSymbolAddress((void**)&qt,   g_qt);
    cudaGetSymbolAddress((void**)&xhi,  g_xhi);
    cudaGetSymbolAddress((void**)&xlo,  g_xlo);
    cudaGetSymbolAddress((void**)&whi,  g_whi);
    cudaGetSymbolAddress((void**)&wlo,  g_wlo);
    cudaGetSymbolAddress((void**)&qh,   g_qhi);
    cudaGetSymbolAddress((void**)&ql,   g_qlo);
    cudaGetSymbolAddress((void**)&kh,   g_khi);
    cudaGetSymbolAddress((void**)&kl,   g_klo);
    cudaGetSymbolAddress((void**)&vh,   g_vhi);
    cudaGetSymbolAddress((void**)&vl,   g_vlo);
    cudaGetSymbolAddress((void**)&kth,  g_kthi);
    cudaGetSymbolAddress((void**)&ktl,  g_ktlo);
    cudaGetSymbolAddress((void**)&qwh,  g_qwhi);
    cudaGetSymbolAddress((void**)&qwl,  g_qwlo);

    const size_t WSZ = (size_t)Hh * Hh;
    cvt_split<<<(TOKS * Hh / 4 + 255) / 256, 256>>>((const float4*)x,
        (__nv_bfloat162*)xhi, (__nv_bfloat162*)xlo, TOKS * Hh / 4);
    cvt_split_w4<<<dim3((WSZ / 4 + 255) / 256, 4), 256>>>(
        (const float4*)Wq, (const float4*)Wk, (const float4*)Wv, (const float4*)Wo,
        whi, wlo);

    cudaFuncSetAttribute(gemm_qkv, cudaFuncAttributeMaxDynamicSharedMemorySize, GEMM_SMEM);
    cudaFuncSetAttribute(gemm_o,   cudaFuncAttributeMaxDynamicSharedMemorySize, GEMM_SMEM);
    gemm_qkv<<<dim3(GN / 128, TOKS / 128, 3), 256, GEMM_SMEM>>>(
        xhi, xlo, whi, wlo, bq, bk, bv, qh, ql, kh, kl, vh, vl);

    cudaFuncSetAttribute(type_kernel3, cudaFuncAttributeMaxDynamicSharedMemorySize, TK_SMEM);
    type_kernel3<<<TOKS / 16, 512, TK_SMEM>>>(x, Wti, bti, temb, Wqt, bqt, Wkt, bkt,
                                              out_tl, qt, kth, ktl);

    qtw_kernel<<<dim3(TOKS / 64, NHh), 256>>>(qt, Wbil, qwh, qwl);

    cudaFuncSetAttribute(attn_hmma, cudaFuncAttributeMaxDynamicSharedMemorySize, ATT_SMEM);
    attn_hmma<<<dim3(Ss / 64, NHh, Bb), 128, ATT_SMEM>>>(qh, ql, kh, kl, vh, vl,
        kth, ktl, qwh, qwl, mask, out_unif, xhi, xlo);

    gemm_o<<<dim3(GN / 128, TOKS / 128), 256, GEMM_SMEM>>>(xhi, xlo,
        whi + 3 * WSZ, wlo + 3 * WSZ, bo, out_y);
}